// round 14
// baseline (speedup 1.0000x reference)
#include <cuda_runtime.h>
#include <cuda_fp16.h>
#include <math.h>
#include <stdint.h>

// ---------------- problem constants ----------------
#define M_NODES 20000
#define D_NODES 8000
#define E_MM    320000
#define E_DD    128000

#define MPAD 20096
#define DPAD 8064

// ---------------- scratch ----------------
__device__ float   g_h   [M_NODES * 256];
__device__ float   g_feat[M_NODES * 256];
__device__ float   g_asrc[M_NODES * 2];
__device__ float   g_adst[M_NODES * 2];
__device__ float   g_X   [M_NODES * 64];
__device__ float   g_t1  [M_NODES * 256];
__device__ float   g_t2  [M_NODES * 128];
__device__ __half  g_xfh [MPAD * 64];
__device__ int     g_rpA [M_NODES + 1];
__device__ int     g_colA[E_MM];
__device__ int     g_curA[M_NODES];
__device__ int     g_degA[M_NODES];
__device__ float   g_waX [4 * 256];          // WaT buffers: s1,d1,s2,d2
__device__ float   g_hY   [D_NODES * 256];
__device__ float   g_featY[D_NODES * 256];
__device__ float   g_asrcY[D_NODES * 2];
__device__ float   g_adstY[D_NODES * 2];
__device__ float   g_XY   [D_NODES * 64];
__device__ float   g_t1Y  [D_NODES * 256];
__device__ float   g_t2Y  [D_NODES * 128];
__device__ __half  g_yfh  [DPAD * 64];
__device__ int     g_rpB  [D_NODES + 1];
__device__ int     g_colB [E_DD];
__device__ int     g_curB [D_NODES];
__device__ int     g_degB [D_NODES];
__device__ float   g_waY [4 * 256];

// ---------------- helpers ----------------
__device__ __forceinline__ uint32_t cvt_tf32(float f) {
    uint32_t r;
    asm("cvt.rna.tf32.f32 %0, %1;" : "=r"(r) : "f"(f));
    return r;
}
__device__ __forceinline__ void mma_tf32(float* d, const uint32_t* a, const uint32_t* b)
{
    asm volatile(
        "mma.sync.aligned.m16n8k8.row.col.f32.tf32.tf32.f32 "
        "{%0,%1,%2,%3}, {%4,%5,%6,%7}, {%8,%9}, {%0,%1,%2,%3};"
        : "+f"(d[0]), "+f"(d[1]), "+f"(d[2]), "+f"(d[3])
        : "r"(a[0]), "r"(a[1]), "r"(a[2]), "r"(a[3]), "r"(b[0]), "r"(b[1]));
}
__device__ __forceinline__ void mma_f16(float* d, const uint32_t* a, const uint32_t* b)
{
    asm volatile(
        "mma.sync.aligned.m16n8k16.row.col.f32.f16.f16.f32 "
        "{%0,%1,%2,%3}, {%4,%5,%6,%7}, {%8,%9}, {%0,%1,%2,%3};"
        : "+f"(d[0]), "+f"(d[1]), "+f"(d[2]), "+f"(d[3])
        : "r"(a[0]), "r"(a[1]), "r"(a[2]), "r"(a[3]), "r"(b[0]), "r"(b[1]));
}

// ============ generic tf32 mma GEMM (128x64 tile) ==========================
#define GSTR 68
__global__ void __launch_bounds__(256) mma_gemm_kernel(
    const float* __restrict__ A, const float* __restrict__ B,
    const float* __restrict__ bias, float* __restrict__ C,
    int N, int K, int Cn, int relu_act, int out_half)
{
    __shared__ uint32_t As[128 * GSTR];
    __shared__ uint32_t Bs[64 * GSTR];

    const int tid = threadIdx.x, wid = tid >> 5, lane = tid & 31;
    const int g = lane >> 2, t = lane & 3;
    const int wm = wid & 3, wn = wid >> 2;
    const int row0 = blockIdx.y * 128, col0 = blockIdx.x * 64;

    float acc[2][4][4];
    #pragma unroll
    for (int i = 0; i < 2; i++)
        #pragma unroll
        for (int j = 0; j < 4; j++)
            #pragma unroll
            for (int q = 0; q < 4; q++) acc[i][j][q] = 0.f;

    for (int k0 = 0; k0 < K; k0 += 64) {
        #pragma unroll
        for (int i = tid; i < 2048; i += 256) {
            int row = i >> 4, c4 = (i & 15) << 2;
            int gm = row0 + row;
            float4 v = make_float4(0.f, 0.f, 0.f, 0.f);
            if (gm < N) v = *(const float4*)(A + (size_t)gm * K + k0 + c4);
            uint32_t* p = &As[row * GSTR + c4];
            p[0] = cvt_tf32(v.x); p[1] = cvt_tf32(v.y);
            p[2] = cvt_tf32(v.z); p[3] = cvt_tf32(v.w);
        }
        #pragma unroll
        for (int i = tid; i < 1024; i += 256) {
            int kk = i >> 4, c4 = (i & 15) << 2;
            float4 v = *(const float4*)(B + (size_t)(k0 + kk) * Cn + col0 + c4);
            Bs[(c4 + 0) * GSTR + kk] = cvt_tf32(v.x);
            Bs[(c4 + 1) * GSTR + kk] = cvt_tf32(v.y);
            Bs[(c4 + 2) * GSTR + kk] = cvt_tf32(v.z);
            Bs[(c4 + 3) * GSTR + kk] = cvt_tf32(v.w);
        }
        __syncthreads();

        #pragma unroll
        for (int ks = 0; ks < 8; ks++) {
            const int kb = ks * 8;
            uint32_t a[2][4];
            #pragma unroll
            for (int mf = 0; mf < 2; mf++) {
                int r = wm * 32 + mf * 16;
                a[mf][0] = As[(r + g)     * GSTR + kb + t];
                a[mf][1] = As[(r + g + 8) * GSTR + kb + t];
                a[mf][2] = As[(r + g)     * GSTR + kb + t + 4];
                a[mf][3] = As[(r + g + 8) * GSTR + kb + t + 4];
            }
            #pragma unroll
            for (int nf = 0; nf < 4; nf++) {
                uint32_t b[2];
                int n = wn * 32 + nf * 8 + g;
                b[0] = Bs[n * GSTR + kb + t];
                b[1] = Bs[n * GSTR + kb + t + 4];
                mma_tf32(acc[0][nf], a[0], b);
                mma_tf32(acc[1][nf], a[1], b);
            }
        }
        __syncthreads();
    }

    #pragma unroll
    for (int mf = 0; mf < 2; mf++) {
        #pragma unroll
        for (int rr = 0; rr < 2; rr++) {
            int row = row0 + wm * 32 + mf * 16 + rr * 8 + g;
            if (row >= N) continue;
            #pragma unroll
            for (int nf = 0; nf < 4; nf++) {
                int col = col0 + wn * 32 + nf * 8 + 2 * t;
                float2 v;
                v.x = acc[mf][nf][rr * 2 + 0];
                v.y = acc[mf][nf][rr * 2 + 1];
                if (bias) { v.x += bias[col]; v.y += bias[col + 1]; }
                if (relu_act) { v.x = fmaxf(v.x, 0.f); v.y = fmaxf(v.y, 0.f); }
                if (out_half) {
                    __half2 hv = __float22half2_rn(v);
                    *(__half2*)((__half*)C + (size_t)row * Cn + col) = hv;
                } else {
                    *(float2*)(C + (size_t)row * Cn + col) = v;
                }
            }
        }
    }
}

// ---------------- CSR build ----------------
__global__ void hist_kernel(const int* __restrict__ dst, int* __restrict__ deg, int E)
{
    int i = blockIdx.x * blockDim.x + threadIdx.x;
    if (i < E) atomicAdd(&deg[dst[i]], 1);
}

__global__ void __launch_bounds__(1024) scan_kernel(const int* __restrict__ deg,
                                                    int* __restrict__ rowptr,
                                                    int* __restrict__ cursor, int N)
{
    __shared__ int sums[32];
    __shared__ int carry;
    int tid = threadIdx.x;
    if (tid == 0) carry = 0;
    __syncthreads();
    for (int base = 0; base < N; base += 1024) {
        int i = base + tid;
        int v = (i < N) ? deg[i] : 0;
        int x = v;
        #pragma unroll
        for (int o = 1; o < 32; o <<= 1) {
            int y = __shfl_up_sync(~0u, x, o);
            if ((tid & 31) >= o) x += y;
        }
        if ((tid & 31) == 31) sums[tid >> 5] = x;
        __syncthreads();
        if (tid < 32) {
            int s = sums[tid];
            #pragma unroll
            for (int o = 1; o < 32; o <<= 1) {
                int y = __shfl_up_sync(~0u, s, o);
                if (tid >= o) s += y;
            }
            sums[tid] = s;
        }
        __syncthreads();
        int incl = x + ((tid >= 32) ? sums[(tid >> 5) - 1] : 0) + carry;
        if (i < N) {
            rowptr[i + 1] = incl;
            cursor[i] = incl - v;
        }
        __syncthreads();
        if (tid == 1023) carry = incl;
        __syncthreads();
    }
    if (tid == 0) rowptr[0] = 0;
}

__global__ void scatter_kernel(const int* __restrict__ src, const int* __restrict__ dst,
                               int* __restrict__ cursor, int* __restrict__ col, int E)
{
    int i = blockIdx.x * blockDim.x + threadIdx.x;
    if (i >= E) return;
    int slot = atomicAdd(&cursor[dst[i]], 1);
    col[slot] = src[i];
}

// ---------------- GAT kernels ----------------
// WaT[h*Fin + k] = sum_c W[k, h*C + c] * a[h, c]   (weights-only precompute)
__global__ void wa_kernel(const float* __restrict__ W, const float* __restrict__ a,
                          float* __restrict__ WaT, int Fin, int H, int C)
{
    int idx = blockIdx.x * blockDim.x + threadIdx.x;
    if (idx >= Fin * H) return;
    int k = idx / H, h = idx % H;
    const float* wp = W + (size_t)k * H * C + h * C;
    const float* ap = a + h * C;
    float s = 0.f;
    for (int c = 0; c < C; c++) s += wp[c] * ap[c];
    WaT[h * Fin + k] = s;
}

// alpha from layer INPUT: asrc[n,h] = x[n,:] . WaS[h,:], adst likewise.
__global__ void alpha_x_kernel(const float* __restrict__ x,
                               const float* __restrict__ WaS,
                               const float* __restrict__ WaD,
                               float* __restrict__ asrc, float* __restrict__ adst,
                               int N, int Fin, int H)
{
    int idx = blockIdx.x * blockDim.x + threadIdx.x;
    if (idx >= N * H) return;
    int n = idx / H, h = idx % H;
    const float* xp = x + (size_t)n * Fin;
    const float* ws = WaS + h * Fin;
    const float* wd = WaD + h * Fin;
    float s1 = 0.f, s2 = 0.f;
    for (int k = 0; k < Fin; k++) { float v = xp[k]; s1 += v * ws[k]; s2 += v * wd[k]; }
    asrc[idx] = s1;
    adst[idx] = s2;
}

template<int H, int CPL>
__global__ void gat_aggregate(const int* __restrict__ rowptr, const int* __restrict__ col,
                              const float* __restrict__ asrc, const float* __restrict__ adst,
                              const float* __restrict__ h, const float* __restrict__ bias,
                              float* __restrict__ out, int N)
{
    const int C = 32 * CPL;
    int warp = (blockIdx.x * blockDim.x + threadIdx.x) >> 5;
    int lane = threadIdx.x & 31;
    if (warp >= N * H) return;
    int d = warp / H, hh = warp % H;
    int beg = rowptr[d], end = rowptr[d + 1];
    float ad = adst[d * H + hh];

    float m = -INFINITY, den = 0.f;
    for (int i = beg + lane; i < end; i += 32) {
        float v = asrc[col[i] * H + hh] + ad;
        v = (v >= 0.f) ? v : 0.2f * v;
        if (v > m) { den = den * __expf(m - v) + 1.f; m = v; }
        else den += __expf(v - m);
    }
    #pragma unroll
    for (int o = 16; o; o >>= 1) {
        float m2 = __shfl_xor_sync(~0u, m, o);
        float d2 = __shfl_xor_sync(~0u, den, o);
        float nm = fmaxf(m, m2);
        float f1 = (m == nm) ? 1.f : __expf(m - nm);
        float f2 = (m2 == nm) ? 1.f : __expf(m2 - nm);
        den = den * f1 + d2 * f2;
        m = nm;
    }
    float inv = 1.f / (den + 1e-16f);

    float acc[CPL];
    #pragma unroll
    for (int q = 0; q < CPL; q++) acc[q] = 0.f;

    for (int base = beg; base < end; base += 32) {
        int i = base + lane;
        int s = 0; float coef = 0.f;
        if (i < end) {
            s = col[i];
            float v = asrc[s * H + hh] + ad;
            v = (v >= 0.f) ? v : 0.2f * v;
            coef = __expf(v - m) * inv;
        }
        int cnt = min(32, end - base);
        for (int j = 0; j < cnt; j++) {
            int sj = __shfl_sync(~0u, s, j);
            float cj = __shfl_sync(~0u, coef, j);
            const float* hp = h + ((size_t)sj * H + hh) * C + lane * CPL;
            if (CPL == 4) {
                float4 v4 = *(const float4*)hp;
                acc[0] += cj * v4.x; acc[1] += cj * v4.y;
                acc[2] += cj * v4.z; acc[3] += cj * v4.w;
            } else {
                float2 v2 = *(const float2*)hp;
                acc[0] += cj * v2.x; acc[1] += cj * v2.y;
            }
        }
    }

    float* op = out + ((size_t)d * H + hh) * C + lane * CPL;
    const float* bp = bias + hh * C + lane * CPL;
    if (CPL == 4) {
        float4 v;
        v.x = fmaxf(acc[0] + bp[0], 0.f); v.y = fmaxf(acc[1] + bp[1], 0.f);
        v.z = fmaxf(acc[2] + bp[2], 0.f); v.w = fmaxf(acc[3] + bp[3], 0.f);
        *(float4*)op = v;
    } else {
        float2 v;
        v.x = fmaxf(acc[0] + bp[0], 0.f); v.y = fmaxf(acc[1] + bp[1], 0.f);
        *(float2*)op = v;
    }
}

// ================= final GEMM: out = xf @ yf^T (fp16 m16n8k16) =============
#define BSTR 72
__global__ void __launch_bounds__(256) final_mma_kernel(
    const __half* __restrict__ A, const __half* __restrict__ B, float* __restrict__ C)
{
    __shared__ __half As[128 * BSTR];
    __shared__ __half Bs[128 * BSTR];

    const int tid = threadIdx.x, wid = tid >> 5, lane = tid & 31;
    const int g = lane >> 2, t = lane & 3;
    const int wm = wid & 3, wn = wid >> 2;
    const int m0 = blockIdx.y * 128, n0 = blockIdx.x * 128;

    {
        const __half* Ag = A + (size_t)m0 * 64;
        const __half* Bg = B + (size_t)n0 * 64;
        #pragma unroll
        for (int i = tid; i < 1024; i += 256) {
            int row = i >> 3, c8 = (i & 7) << 3;
            uint4 v = *(const uint4*)(Ag + (size_t)row * 64 + c8);
            *(uint4*)&As[row * BSTR + c8] = v;
        }
        #pragma unroll
        for (int i = tid; i < 1024; i += 256) {
            int row = i >> 3, c8 = (i & 7) << 3;
            uint4 v = *(const uint4*)(Bg + (size_t)row * 64 + c8);
            *(uint4*)&Bs[row * BSTR + c8] = v;
        }
    }
    __syncthreads();

    float acc[2][8][4];
    #pragma unroll
    for (int i = 0; i < 2; i++)
        #pragma unroll
        for (int j = 0; j < 8; j++)
            #pragma unroll
            for (int q = 0; q < 4; q++) acc[i][j][q] = 0.f;

    #pragma unroll
    for (int ks = 0; ks < 4; ks++) {
        const int kb = ks * 16;
        uint32_t a[2][4];
        #pragma unroll
        for (int mf = 0; mf < 2; mf++) {
            int r = wm * 32 + mf * 16;
            a[mf][0] = *(const uint32_t*)&As[(r + g)     * BSTR + kb + 2 * t];
            a[mf][1] = *(const uint32_t*)&As[(r + g + 8) * BSTR + kb + 2 * t];
            a[mf][2] = *(const uint32_t*)&As[(r + g)     * BSTR + kb + 2 * t + 8];
            a[mf][3] = *(const uint32_t*)&As[(r + g + 8) * BSTR + kb + 2 * t + 8];
        }
        #pragma unroll
        for (int nf = 0; nf < 8; nf++) {
            int n = wn * 64 + nf * 8 + g;
            uint32_t b[2];
            b[0] = *(const uint32_t*)&Bs[n * BSTR + kb + 2 * t];
            b[1] = *(const uint32_t*)&Bs[n * BSTR + kb + 2 * t + 8];
            mma_f16(acc[0][nf], a[0], b);
            mma_f16(acc[1][nf], a[1], b);
        }
    }

    #pragma unroll
    for (int mf = 0; mf < 2; mf++) {
        #pragma unroll
        for (int rr = 0; rr < 2; rr++) {
            int row = m0 + wm * 32 + mf * 16 + rr * 8 + g;
            if (row >= M_NODES) continue;
            float* cp = C + (size_t)row * D_NODES;
            #pragma unroll
            for (int nf = 0; nf < 8; nf++) {
                int col = n0 + wn * 64 + nf * 8 + 2 * t;
                if (col < D_NODES) {
                    float2 v;
                    v.x = acc[mf][nf][rr * 2 + 0];
                    v.y = acc[mf][nf][rr * 2 + 1];
                    *(float2*)(cp + col) = v;
                }
            }
        }
    }
}

// ---------------- host orchestration ----------------
static void run_gemm(const float* A, const float* B, const float* bias, float* C,
                     int N, int K, int Cn, int act, cudaStream_t st, int out_half = 0)
{
    dim3 g(Cn / 64, (N + 127) / 128);
    mma_gemm_kernel<<<g, 256, 0, st>>>(A, B, bias, C, N, K, Cn, act, out_half);
}

static void build_csr(const int* ei, int E, int N, int* rowptr, int* col,
                      int* cursor, int* deg, cudaStream_t st)
{
    const int* src = ei;
    const int* dst = ei + E;
    cudaMemsetAsync(deg, 0, N * sizeof(int), st);
    hist_kernel<<<(E + 255) / 256, 256, 0, st>>>(dst, deg, E);
    scan_kernel<<<1, 1024, 0, st>>>(deg, rowptr, cursor, N);
    scatter_kernel<<<(E + 255) / 256, 256, 0, st>>>(src, dst, cursor, col, E);
}

extern "C" void kernel_launch(void* const* d_in, const int* in_sizes, int n_in,
                              void* d_out, int out_size)
{
    const float* x_m  = (const float*)d_in[0];
    const float* x_d  = (const float*)d_in[1];
    const int*   mm   = (const int*)d_in[2];
    const int*   dd   = (const int*)d_in[3];
    const float* W_gx1 = (const float*)d_in[4];
    const float* as_gx1 = (const float*)d_in[5];
    const float* ad_gx1 = (const float*)d_in[6];
    const float* b_gx1  = (const float*)d_in[7];
    const float* W_gx2 = (const float*)d_in[8];
    const float* as_gx2 = (const float*)d_in[9];
    const float* ad_gx2 = (const float*)d_in[10];
    const float* b_gx2  = (const float*)d_in[11];
    const float* W_gy1 = (const float*)d_in[12];
    const float* as_gy1 = (const float*)d_in[13];
    const float* ad_gy1 = (const float*)d_in[14];
    const float* b_gy1  = (const float*)d_in[15];
    const float* W_gy2 = (const float*)d_in[16];
    const float* as_gy2 = (const float*)d_in[17];
    const float* ad_gy2 = (const float*)d_in[18];
    const float* b_gy2  = (const float*)d_in[19];
    const float* lx1_W = (const float*)d_in[20];
    const float* lx1_b = (const float*)d_in[21];
    const float* lx2_W = (const float*)d_in[22];
    const float* lx2_b = (const float*)d_in[23];
    const float* lx3_W = (const float*)d_in[24];
    const float* lx3_b = (const float*)d_in[25];
    const float* ly1_W = (const float*)d_in[26];
    const float* ly1_b = (const float*)d_in[27];
    const float* ly2_W = (const float*)d_in[28];
    const float* ly2_b = (const float*)d_in[29];
    const float* ly3_W = (const float*)d_in[30];
    const float* ly3_b = (const float*)d_in[31];

    float *h, *feat, *asrc, *adst, *X, *t1, *t2, *waX;
    float *hY, *featY, *asrcY, *adstY, *XY, *t1Y, *t2Y, *waY;
    __half *xfh, *yfh;
    int *rpA, *colA, *curA, *degA, *rpB, *colB, *curB, *degB;
    cudaGetSymbolAddress((void**)&h,    g_h);
    cudaGetSymbolAddress((void**)&feat, g_feat);
    cudaGetSymbolAddress((void**)&asrc, g_asrc);
    cudaGetSymbolAddress((void**)&adst, g_adst);
    cudaGetSymbolAddress((void**)&X,    g_X);
    cudaGetSymbolAddress((void**)&t1,   g_t1);
    cudaGetSymbolAddress((void**)&t2,   g_t2);
    cudaGetSymbolAddress((void**)&xfh,  g_xfh);
    cudaGetSymbolAddress((void**)&rpA,  g_rpA);
    cudaGetSymbolAddress((void**)&colA, g_colA);
    cudaGetSymbolAddress((void**)&curA, g_curA);
    cudaGetSymbolAddress((void**)&degA, g_degA);
    cudaGetSymbolAddress((void**)&waX,  g_waX);
    cudaGetSymbolAddress((void**)&hY,    g_hY);
    cudaGetSymbolAddress((void**)&featY, g_featY);
    cudaGetSymbolAddress((void**)&asrcY, g_asrcY);
    cudaGetSymbolAddress((void**)&adstY, g_adstY);
    cudaGetSymbolAddress((void**)&XY,    g_XY);
    cudaGetSymbolAddress((void**)&t1Y,   g_t1Y);
    cudaGetSymbolAddress((void**)&t2Y,   g_t2Y);
    cudaGetSymbolAddress((void**)&yfh,   g_yfh);
    cudaGetSymbolAddress((void**)&rpB,  g_rpB);
    cudaGetSymbolAddress((void**)&colB, g_colB);
    cudaGetSymbolAddress((void**)&curB, g_curB);
    cudaGetSymbolAddress((void**)&degB, g_degB);
    cudaGetSymbolAddress((void**)&waY,  g_waY);

    static cudaStream_t sY = 0, sC = 0;
    static cudaEvent_t eFork = 0, eJoin = 0, eCsr = 0, eFeat = 0, eA2 = 0;
    static bool inited = false, forked = false;
    if (!inited) {
        inited = true;
        forked = (cudaStreamCreateWithFlags(&sY, cudaStreamNonBlocking) == cudaSuccess)
              && (cudaStreamCreateWithFlags(&sC, cudaStreamNonBlocking) == cudaSuccess)
              && (cudaEventCreateWithFlags(&eFork, cudaEventDisableTiming) == cudaSuccess)
              && (cudaEventCreateWithFlags(&eJoin, cudaEventDisableTiming) == cudaSuccess)
              && (cudaEventCreateWithFlags(&eCsr,  cudaEventDisableTiming) == cudaSuccess)
              && (cudaEventCreateWithFlags(&eFeat, cudaEventDisableTiming) == cudaSuccess)
              && (cudaEventCreateWithFlags(&eA2,   cudaEventDisableTiming) == cudaSuccess);
    }
    cudaStream_t sy = forked ? sY : 0;
    cudaStream_t sc = forked ? sC : 0;
    if (forked) {
        cudaEventRecord(eFork, 0);
        cudaStreamWaitEvent(sY, eFork, 0);
        cudaStreamWaitEvent(sC, eFork, 0);
    }

    // ----- X side stream: Wa precompute, CSR build, alpha1 (input-only deps) -----
    wa_kernel<<<1, 128, 0, sc>>>(W_gx1, as_gx1, waX + 0,   64, 2, 128);
    wa_kernel<<<1, 128, 0, sc>>>(W_gx1, ad_gx1, waX + 256, 64, 2, 128);
    wa_kernel<<<1, 256, 0, sc>>>(W_gx2, as_gx2, waX + 512, 256, 1, 64);
    wa_kernel<<<1, 256, 0, sc>>>(W_gx2, ad_gx2, waX + 768, 256, 1, 64);
    build_csr(mm, E_MM, M_NODES, rpA, colA, curA, degA, sc);
    alpha_x_kernel<<<(M_NODES * 2 + 255) / 256, 256, 0, sc>>>(
        x_m, waX + 0, waX + 256, asrc, adst, M_NODES, 64, 2);
    if (forked) cudaEventRecord(eCsr, sC);

    // ----- X branch (stream 0) -----
    cudaMemsetAsync(xfh + (size_t)M_NODES * 64, 0,
                    (size_t)(MPAD - M_NODES) * 64 * sizeof(__half), 0);
    run_gemm(x_m, W_gx1, nullptr, h, M_NODES, 64, 256, 0, 0);
    if (forked) cudaStreamWaitEvent(0, eCsr, 0);
    gat_aggregate<2, 4><<<(M_NODES * 2 + 7) / 8, 256, 0, 0>>>(rpA, colA, asrc, adst, h, b_gx1, feat, M_NODES);
    if (forked) {
        cudaEventRecord(eFeat, 0);
        cudaStreamWaitEvent(sC, eFeat, 0);
    }
    // alpha2 on side stream, concurrent with projection GEMM 2
    alpha_x_kernel<<<(M_NODES + 255) / 256, 256, 0, sc>>>(
        feat, waX + 512, waX + 768, asrc, adst, M_NODES, 256, 1);
    if (forked) cudaEventRecord(eA2, sC);
    run_gemm(feat, W_gx2, nullptr, h, M_NODES, 256, 64, 0, 0);
    if (forked) cudaStreamWaitEvent(0, eA2, 0);
    gat_aggregate<1, 2><<<(M_NODES + 7) / 8, 256, 0, 0>>>(rpA, colA, asrc, adst, h, b_gx2, X, M_NODES);
    run_gemm(X,  lx1_W, lx1_b, t1, M_NODES, 64,  256, 1, 0);
    run_gemm(t1, lx2_W, lx2_b, t2, M_NODES, 256, 128, 1, 0);
    run_gemm(t2, lx3_W, lx3_b, (float*)xfh, M_NODES, 128, 64, 1, 0, 1);

    // ----- Y branch (side stream sy, serial within) -----
    cudaMemsetAsync(yfh + (size_t)D_NODES * 64, 0,
                    (size_t)(DPAD - D_NODES) * 64 * sizeof(__half), sy);
    wa_kernel<<<1, 128, 0, sy>>>(W_gy1, as_gy1, waY + 0,   64, 2, 128);
    wa_kernel<<<1, 128, 0, sy>>>(W_gy1, ad_gy1, waY + 256, 64, 2, 128);
    wa_kernel<<<1, 256, 0, sy>>>(W_gy2, as_gy2, waY + 512, 256, 1, 64);
    wa_kernel<<<1, 256, 0, sy>>>(W_gy2, ad_gy2, waY + 768, 256, 1, 64);
    build_csr(dd, E_DD, D_NODES, rpB, colB, curB, degB, sy);
    alpha_x_kernel<<<(D_NODES * 2 + 255) / 256, 256, 0, sy>>>(
        x_d, waY + 0, waY + 256, asrcY, adstY, D_NODES, 64, 2);
    run_gemm(x_d, W_gy1, nullptr, hY, D_NODES, 64, 256, 0, sy);
    gat_aggregate<2, 4><<<(D_NODES * 2 + 7) / 8, 256, 0, sy>>>(rpB, colB, asrcY, adstY, hY, b_gy1, featY, D_NODES);
    alpha_x_kernel<<<(D_NODES + 255) / 256, 256, 0, sy>>>(
        featY, waY + 512, waY + 768, asrcY, adstY, D_NODES, 256, 1);
    run_gemm(featY, W_gy2, nullptr, hY, D_NODES, 256, 64, 0, sy);
    gat_aggregate<1, 2><<<(D_NODES + 7) / 8, 256, 0, sy>>>(rpB, colB, asrcY, adstY, hY, b_gy2, XY, D_NODES);
    run_gemm(XY,  ly1_W, ly1_b, t1Y, D_NODES, 64,  256, 1, sy);
    run_gemm(t1Y, ly2_W, ly2_b, t2Y, D_NODES, 256, 128, 1, sy);
    run_gemm(t1Y == nullptr ? nullptr : t2Y, ly3_W, ly3_b, (float*)yfh, D_NODES, 128, 64, 1, sy, 1);

    if (forked) {
        cudaEventRecord(eJoin, sY);
        cudaStreamWaitEvent(0, eJoin, 0);
    }

    // ----- final: out = xf @ yf^T (fp16 operands, f32 accum/output) -----
    dim3 grid(DPAD / 128, MPAD / 128);   // 63 x 157
    final_mma_kernel<<<grid, 256, 0, 0>>>(xfh, yfh, (float*)d_out);
}

// round 15
// speedup vs baseline: 1.3750x; 1.3750x over previous
#include <cuda_runtime.h>
#include <cuda_fp16.h>
#include <math.h>
#include <stdint.h>

// ---------------- problem constants ----------------
#define M_NODES 20000
#define D_NODES 8000
#define E_MM    320000
#define E_DD    128000

#define MPAD 20096
#define DPAD 8064

// ---------------- scratch ----------------
__device__ float   g_h   [M_NODES * 256];
__device__ float   g_feat[M_NODES * 256];
__device__ float   g_asrc[M_NODES * 2];
__device__ float   g_adst[M_NODES * 2];
__device__ float   g_X   [M_NODES * 64];
__device__ float   g_t1  [M_NODES * 256];
__device__ float   g_t2  [M_NODES * 128];
__device__ __half  g_xfh [MPAD * 64];
__device__ int     g_rpA [M_NODES + 1];
__device__ int     g_colA[E_MM];
__device__ int     g_curA[M_NODES];
__device__ int     g_degA[M_NODES];
__device__ float   g_hY   [D_NODES * 256];
__device__ float   g_featY[D_NODES * 256];
__device__ float   g_asrcY[D_NODES * 2];
__device__ float   g_adstY[D_NODES * 2];
__device__ float   g_XY   [D_NODES * 64];
__device__ float   g_t1Y  [D_NODES * 256];
__device__ float   g_t2Y  [D_NODES * 128];
__device__ __half  g_yfh  [DPAD * 64];
__device__ int     g_rpB  [D_NODES + 1];
__device__ int     g_colB [E_DD];
__device__ int     g_curB [D_NODES];
__device__ int     g_degB [D_NODES];

// ---------------- helpers ----------------
__device__ __forceinline__ uint32_t cvt_tf32(float f) {
    uint32_t r;
    asm("cvt.rna.tf32.f32 %0, %1;" : "=r"(r) : "f"(f));
    return r;
}
__device__ __forceinline__ void mma_tf32(float* d, const uint32_t* a, const uint32_t* b)
{
    asm volatile(
        "mma.sync.aligned.m16n8k8.row.col.f32.tf32.tf32.f32 "
        "{%0,%1,%2,%3}, {%4,%5,%6,%7}, {%8,%9}, {%0,%1,%2,%3};"
        : "+f"(d[0]), "+f"(d[1]), "+f"(d[2]), "+f"(d[3])
        : "r"(a[0]), "r"(a[1]), "r"(a[2]), "r"(a[3]), "r"(b[0]), "r"(b[1]));
}
__device__ __forceinline__ void mma_f16(float* d, const uint32_t* a, const uint32_t* b)
{
    asm volatile(
        "mma.sync.aligned.m16n8k16.row.col.f32.f16.f16.f32 "
        "{%0,%1,%2,%3}, {%4,%5,%6,%7}, {%8,%9}, {%0,%1,%2,%3};"
        : "+f"(d[0]), "+f"(d[1]), "+f"(d[2]), "+f"(d[3])
        : "r"(a[0]), "r"(a[1]), "r"(a[2]), "r"(a[3]), "r"(b[0]), "r"(b[1]));
}

// ============ generic tf32 mma GEMM (128x64 tile) ==========================
// Optional fused alpha: if a_s != nullptr, per-row partial dots of the output
// tile against a_src/a_dst are atomically accumulated into asrc/adst.
// Requires: each 64-col tile lies within one head (Chead in {64,128}).
#define GSTR 68
__global__ void __launch_bounds__(256) mma_gemm_kernel(
    const float* __restrict__ A, const float* __restrict__ B,
    const float* __restrict__ bias, float* __restrict__ C,
    int N, int K, int Cn, int relu_act, int out_half,
    const float* __restrict__ a_s, const float* __restrict__ a_d,
    float* __restrict__ asrc, float* __restrict__ adst, int H, int Chead)
{
    __shared__ uint32_t As[128 * GSTR];
    __shared__ uint32_t Bs[64 * GSTR];

    const int tid = threadIdx.x, wid = tid >> 5, lane = tid & 31;
    const int g = lane >> 2, t = lane & 3;
    const int wm = wid & 3, wn = wid >> 2;
    const int row0 = blockIdx.y * 128, col0 = blockIdx.x * 64;

    float acc[2][4][4];
    #pragma unroll
    for (int i = 0; i < 2; i++)
        #pragma unroll
        for (int j = 0; j < 4; j++)
            #pragma unroll
            for (int q = 0; q < 4; q++) acc[i][j][q] = 0.f;

    for (int k0 = 0; k0 < K; k0 += 64) {
        #pragma unroll
        for (int i = tid; i < 2048; i += 256) {
            int row = i >> 4, c4 = (i & 15) << 2;
            int gm = row0 + row;
            float4 v = make_float4(0.f, 0.f, 0.f, 0.f);
            if (gm < N) v = *(const float4*)(A + (size_t)gm * K + k0 + c4);
            uint32_t* p = &As[row * GSTR + c4];
            p[0] = cvt_tf32(v.x); p[1] = cvt_tf32(v.y);
            p[2] = cvt_tf32(v.z); p[3] = cvt_tf32(v.w);
        }
        #pragma unroll
        for (int i = tid; i < 1024; i += 256) {
            int kk = i >> 4, c4 = (i & 15) << 2;
            float4 v = *(const float4*)(B + (size_t)(k0 + kk) * Cn + col0 + c4);
            Bs[(c4 + 0) * GSTR + kk] = cvt_tf32(v.x);
            Bs[(c4 + 1) * GSTR + kk] = cvt_tf32(v.y);
            Bs[(c4 + 2) * GSTR + kk] = cvt_tf32(v.z);
            Bs[(c4 + 3) * GSTR + kk] = cvt_tf32(v.w);
        }
        __syncthreads();

        #pragma unroll
        for (int ks = 0; ks < 8; ks++) {
            const int kb = ks * 8;
            uint32_t a[2][4];
            #pragma unroll
            for (int mf = 0; mf < 2; mf++) {
                int r = wm * 32 + mf * 16;
                a[mf][0] = As[(r + g)     * GSTR + kb + t];
                a[mf][1] = As[(r + g + 8) * GSTR + kb + t];
                a[mf][2] = As[(r + g)     * GSTR + kb + t + 4];
                a[mf][3] = As[(r + g + 8) * GSTR + kb + t + 4];
            }
            #pragma unroll
            for (int nf = 0; nf < 4; nf++) {
                uint32_t b[2];
                int n = wn * 32 + nf * 8 + g;
                b[0] = Bs[n * GSTR + kb + t];
                b[1] = Bs[n * GSTR + kb + t + 4];
                mma_tf32(acc[0][nf], a[0], b);
                mma_tf32(acc[1][nf], a[1], b);
            }
        }
        __syncthreads();
    }

    const int head = (a_s != nullptr) ? (col0 / Chead) : 0;

    #pragma unroll
    for (int mf = 0; mf < 2; mf++) {
        #pragma unroll
        for (int rr = 0; rr < 2; rr++) {
            int row = row0 + wm * 32 + mf * 16 + rr * 8 + g;
            if (row >= N) continue;
            float s1 = 0.f, s2 = 0.f;
            #pragma unroll
            for (int nf = 0; nf < 4; nf++) {
                int col = col0 + wn * 32 + nf * 8 + 2 * t;
                float2 v;
                v.x = acc[mf][nf][rr * 2 + 0];
                v.y = acc[mf][nf][rr * 2 + 1];
                if (a_s) {
                    int c = col - head * Chead;
                    const float* asp = a_s + head * Chead;
                    const float* adp = a_d + head * Chead;
                    s1 += v.x * asp[c] + v.y * asp[c + 1];
                    s2 += v.x * adp[c] + v.y * adp[c + 1];
                }
                if (bias) { v.x += bias[col]; v.y += bias[col + 1]; }
                if (relu_act) { v.x = fmaxf(v.x, 0.f); v.y = fmaxf(v.y, 0.f); }
                if (out_half) {
                    __half2 hv = __float22half2_rn(v);
                    *(__half2*)((__half*)C + (size_t)row * Cn + col) = hv;
                } else {
                    *(float2*)(C + (size_t)row * Cn + col) = v;
                }
            }
            if (a_s) {
                atomicAdd(&asrc[row * H + head], s1);
                atomicAdd(&adst[row * H + head], s2);
            }
        }
    }
}

// ---------------- CSR build ----------------
__global__ void hist_kernel(const int* __restrict__ dst, int* __restrict__ deg, int E)
{
    int i = blockIdx.x * blockDim.x + threadIdx.x;
    if (i < E) atomicAdd(&deg[dst[i]], 1);
}

__global__ void __launch_bounds__(1024) scan_kernel(const int* __restrict__ deg,
                                                    int* __restrict__ rowptr,
                                                    int* __restrict__ cursor, int N)
{
    __shared__ int sums[32];
    __shared__ int carry;
    int tid = threadIdx.x;
    if (tid == 0) carry = 0;
    __syncthreads();
    for (int base = 0; base < N; base += 1024) {
        int i = base + tid;
        int v = (i < N) ? deg[i] : 0;
        int x = v;
        #pragma unroll
        for (int o = 1; o < 32; o <<= 1) {
            int y = __shfl_up_sync(~0u, x, o);
            if ((tid & 31) >= o) x += y;
        }
        if ((tid & 31) == 31) sums[tid >> 5] = x;
        __syncthreads();
        if (tid < 32) {
            int s = sums[tid];
            #pragma unroll
            for (int o = 1; o < 32; o <<= 1) {
                int y = __shfl_up_sync(~0u, s, o);
                if (tid >= o) s += y;
            }
            sums[tid] = s;
        }
        __syncthreads();
        int incl = x + ((tid >= 32) ? sums[(tid >> 5) - 1] : 0) + carry;
        if (i < N) {
            rowptr[i + 1] = incl;
            cursor[i] = incl - v;
        }
        __syncthreads();
        if (tid == 1023) carry = incl;
        __syncthreads();
    }
    if (tid == 0) rowptr[0] = 0;
}

__global__ void scatter_kernel(const int* __restrict__ src, const int* __restrict__ dst,
                               int* __restrict__ cursor, int* __restrict__ col, int E)
{
    int i = blockIdx.x * blockDim.x + threadIdx.x;
    if (i >= E) return;
    int slot = atomicAdd(&cursor[dst[i]], 1);
    col[slot] = src[i];
}

// ---------------- GAT aggregate ----------------
template<int H, int CPL>
__global__ void gat_aggregate(const int* __restrict__ rowptr, const int* __restrict__ col,
                              const float* __restrict__ asrc, const float* __restrict__ adst,
                              const float* __restrict__ h, const float* __restrict__ bias,
                              float* __restrict__ out, int N)
{
    const int C = 32 * CPL;
    int warp = (blockIdx.x * blockDim.x + threadIdx.x) >> 5;
    int lane = threadIdx.x & 31;
    if (warp >= N * H) return;
    int d = warp / H, hh = warp % H;
    int beg = rowptr[d], end = rowptr[d + 1];
    float ad = adst[d * H + hh];

    float m = -INFINITY, den = 0.f;
    for (int i = beg + lane; i < end; i += 32) {
        float v = asrc[col[i] * H + hh] + ad;
        v = (v >= 0.f) ? v : 0.2f * v;
        if (v > m) { den = den * __expf(m - v) + 1.f; m = v; }
        else den += __expf(v - m);
    }
    #pragma unroll
    for (int o = 16; o; o >>= 1) {
        float m2 = __shfl_xor_sync(~0u, m, o);
        float d2 = __shfl_xor_sync(~0u, den, o);
        float nm = fmaxf(m, m2);
        float f1 = (m == nm) ? 1.f : __expf(m - nm);
        float f2 = (m2 == nm) ? 1.f : __expf(m2 - nm);
        den = den * f1 + d2 * f2;
        m = nm;
    }
    float inv = 1.f / (den + 1e-16f);

    float acc[CPL];
    #pragma unroll
    for (int q = 0; q < CPL; q++) acc[q] = 0.f;

    for (int base = beg; base < end; base += 32) {
        int i = base + lane;
        int s = 0; float coef = 0.f;
        if (i < end) {
            s = col[i];
            float v = asrc[s * H + hh] + ad;
            v = (v >= 0.f) ? v : 0.2f * v;
            coef = __expf(v - m) * inv;
        }
        int cnt = min(32, end - base);
        for (int j = 0; j < cnt; j++) {
            int sj = __shfl_sync(~0u, s, j);
            float cj = __shfl_sync(~0u, coef, j);
            const float* hp = h + ((size_t)sj * H + hh) * C + lane * CPL;
            if (CPL == 4) {
                float4 v4 = *(const float4*)hp;
                acc[0] += cj * v4.x; acc[1] += cj * v4.y;
                acc[2] += cj * v4.z; acc[3] += cj * v4.w;
            } else {
                float2 v2 = *(const float2*)hp;
                acc[0] += cj * v2.x; acc[1] += cj * v2.y;
            }
        }
    }

    float* op = out + ((size_t)d * H + hh) * C + lane * CPL;
    const float* bp = bias + hh * C + lane * CPL;
    if (CPL == 4) {
        float4 v;
        v.x = fmaxf(acc[0] + bp[0], 0.f); v.y = fmaxf(acc[1] + bp[1], 0.f);
        v.z = fmaxf(acc[2] + bp[2], 0.f); v.w = fmaxf(acc[3] + bp[3], 0.f);
        *(float4*)op = v;
    } else {
        float2 v;
        v.x = fmaxf(acc[0] + bp[0], 0.f); v.y = fmaxf(acc[1] + bp[1], 0.f);
        *(float2*)op = v;
    }
}

// ================= final GEMM: out = xf @ yf^T (fp16 m16n8k16) =============
#define BSTR 72
__global__ void __launch_bounds__(256) final_mma_kernel(
    const __half* __restrict__ A, const __half* __restrict__ B, float* __restrict__ C)
{
    __shared__ __half As[128 * BSTR];
    __shared__ __half Bs[128 * BSTR];

    const int tid = threadIdx.x, wid = tid >> 5, lane = tid & 31;
    const int g = lane >> 2, t = lane & 3;
    const int wm = wid & 3, wn = wid >> 2;
    const int m0 = blockIdx.y * 128, n0 = blockIdx.x * 128;

    {
        const __half* Ag = A + (size_t)m0 * 64;
        const __half* Bg = B + (size_t)n0 * 64;
        #pragma unroll
        for (int i = tid; i < 1024; i += 256) {
            int row = i >> 3, c8 = (i & 7) << 3;
            uint4 v = *(const uint4*)(Ag + (size_t)row * 64 + c8);
            *(uint4*)&As[row * BSTR + c8] = v;
        }
        #pragma unroll
        for (int i = tid; i < 1024; i += 256) {
            int row = i >> 3, c8 = (i & 7) << 3;
            uint4 v = *(const uint4*)(Bg + (size_t)row * 64 + c8);
            *(uint4*)&Bs[row * BSTR + c8] = v;
        }
    }
    __syncthreads();

    float acc[2][8][4];
    #pragma unroll
    for (int i = 0; i < 2; i++)
        #pragma unroll
        for (int j = 0; j < 8; j++)
            #pragma unroll
            for (int q = 0; q < 4; q++) acc[i][j][q] = 0.f;

    #pragma unroll
    for (int ks = 0; ks < 4; ks++) {
        const int kb = ks * 16;
        uint32_t a[2][4];
        #pragma unroll
        for (int mf = 0; mf < 2; mf++) {
            int r = wm * 32 + mf * 16;
            a[mf][0] = *(const uint32_t*)&As[(r + g)     * BSTR + kb + 2 * t];
            a[mf][1] = *(const uint32_t*)&As[(r + g + 8) * BSTR + kb + 2 * t];
            a[mf][2] = *(const uint32_t*)&As[(r + g)     * BSTR + kb + 2 * t + 8];
            a[mf][3] = *(const uint32_t*)&As[(r + g + 8) * BSTR + kb + 2 * t + 8];
        }
        #pragma unroll
        for (int nf = 0; nf < 8; nf++) {
            int n = wn * 64 + nf * 8 + g;
            uint32_t b[2];
            b[0] = *(const uint32_t*)&Bs[n * BSTR + kb + 2 * t];
            b[1] = *(const uint32_t*)&Bs[n * BSTR + kb + 2 * t + 8];
            mma_f16(acc[0][nf], a[0], b);
            mma_f16(acc[1][nf], a[1], b);
        }
    }

    #pragma unroll
    for (int mf = 0; mf < 2; mf++) {
        #pragma unroll
        for (int rr = 0; rr < 2; rr++) {
            int row = m0 + wm * 32 + mf * 16 + rr * 8 + g;
            if (row >= M_NODES) continue;
            float* cp = C + (size_t)row * D_NODES;
            #pragma unroll
            for (int nf = 0; nf < 8; nf++) {
                int col = n0 + wn * 64 + nf * 8 + 2 * t;
                if (col < D_NODES) {
                    float2 v;
                    v.x = acc[mf][nf][rr * 2 + 0];
                    v.y = acc[mf][nf][rr * 2 + 1];
                    *(float2*)(cp + col) = v;
                }
            }
        }
    }
}

// ---------------- host orchestration ----------------
static void run_gemm(const float* A, const float* B, const float* bias, float* C,
                     int N, int K, int Cn, int act, cudaStream_t st, int out_half = 0,
                     const float* a_s = nullptr, const float* a_d = nullptr,
                     float* asrc = nullptr, float* adst = nullptr,
                     int H = 1, int Chead = 64)
{
    dim3 g(Cn / 64, (N + 127) / 128);
    mma_gemm_kernel<<<g, 256, 0, st>>>(A, B, bias, C, N, K, Cn, act, out_half,
                                       a_s, a_d, asrc, adst, H, Chead);
}

static void build_csr(const int* ei, int E, int N, int* rowptr, int* col,
                      int* cursor, int* deg, cudaStream_t st)
{
    const int* src = ei;
    const int* dst = ei + E;
    cudaMemsetAsync(deg, 0, N * sizeof(int), st);
    hist_kernel<<<(E + 255) / 256, 256, 0, st>>>(dst, deg, E);
    scan_kernel<<<1, 1024, 0, st>>>(deg, rowptr, cursor, N);
    scatter_kernel<<<(E + 255) / 256, 256, 0, st>>>(src, dst, cursor, col, E);
}

extern "C" void kernel_launch(void* const* d_in, const int* in_sizes, int n_in,
                              void* d_out, int out_size)
{
    const float* x_m  = (const float*)d_in[0];
    const float* x_d  = (const float*)d_in[1];
    const int*   mm   = (const int*)d_in[2];
    const int*   dd   = (const int*)d_in[3];
    const float* W_gx1 = (const float*)d_in[4];
    const float* as_gx1 = (const float*)d_in[5];
    const float* ad_gx1 = (const float*)d_in[6];
    const float* b_gx1  = (const float*)d_in[7];
    const float* W_gx2 = (const float*)d_in[8];
    const float* as_gx2 = (const float*)d_in[9];
    const float* ad_gx2 = (const float*)d_in[10];
    const float* b_gx2  = (const float*)d_in[11];
    const float* W_gy1 = (const float*)d_in[12];
    const float* as_gy1 = (const float*)d_in[13];
    const float* ad_gy1 = (const float*)d_in[14];
    const float* b_gy1  = (const float*)d_in[15];
    const float* W_gy2 = (const float*)d_in[16];
    const float* as_gy2 = (const float*)d_in[17];
    const float* ad_gy2 = (const float*)d_in[18];
    const float* b_gy2  = (const float*)d_in[19];
    const float* lx1_W = (const float*)d_in[20];
    const float* lx1_b = (const float*)d_in[21];
    const float* lx2_W = (const float*)d_in[22];
    const float* lx2_b = (const float*)d_in[23];
    const float* lx3_W = (const float*)d_in[24];
    const float* lx3_b = (const float*)d_in[25];
    const float* ly1_W = (const float*)d_in[26];
    const float* ly1_b = (const float*)d_in[27];
    const float* ly2_W = (const float*)d_in[28];
    const float* ly2_b = (const float*)d_in[29];
    const float* ly3_W = (const float*)d_in[30];
    const float* ly3_b = (const float*)d_in[31];

    float *h, *feat, *asrc, *adst, *X, *t1, *t2;
    float *hY, *featY, *asrcY, *adstY, *XY, *t1Y, *t2Y;
    __half *xfh, *yfh;
    int *rpA, *colA, *curA, *degA, *rpB, *colB, *curB, *degB;
    cudaGetSymbolAddress((void**)&h,    g_h);
    cudaGetSymbolAddress((void**)&feat, g_feat);
    cudaGetSymbolAddress((void**)&asrc, g_asrc);
    cudaGetSymbolAddress((void**)&adst, g_adst);
    cudaGetSymbolAddress((void**)&X,    g_X);
    cudaGetSymbolAddress((void**)&t1,   g_t1);
    cudaGetSymbolAddress((void**)&t2,   g_t2);
    cudaGetSymbolAddress((void**)&xfh,  g_xfh);
    cudaGetSymbolAddress((void**)&rpA,  g_rpA);
    cudaGetSymbolAddress((void**)&colA, g_colA);
    cudaGetSymbolAddress((void**)&curA, g_curA);
    cudaGetSymbolAddress((void**)&degA, g_degA);
    cudaGetSymbolAddress((void**)&hY,    g_hY);
    cudaGetSymbolAddress((void**)&featY, g_featY);
    cudaGetSymbolAddress((void**)&asrcY, g_asrcY);
    cudaGetSymbolAddress((void**)&adstY, g_adstY);
    cudaGetSymbolAddress((void**)&XY,    g_XY);
    cudaGetSymbolAddress((void**)&t1Y,   g_t1Y);
    cudaGetSymbolAddress((void**)&t2Y,   g_t2Y);
    cudaGetSymbolAddress((void**)&yfh,   g_yfh);
    cudaGetSymbolAddress((void**)&rpB,  g_rpB);
    cudaGetSymbolAddress((void**)&colB, g_colB);
    cudaGetSymbolAddress((void**)&curB, g_curB);
    cudaGetSymbolAddress((void**)&degB, g_degB);

    static cudaStream_t sY = 0, sC = 0;
    static cudaEvent_t eFork = 0, eJoin = 0, eCsr = 0;
    static bool inited = false, forked = false;
    if (!inited) {
        inited = true;
        forked = (cudaStreamCreateWithFlags(&sY, cudaStreamNonBlocking) == cudaSuccess)
              && (cudaStreamCreateWithFlags(&sC, cudaStreamNonBlocking) == cudaSuccess)
              && (cudaEventCreateWithFlags(&eFork, cudaEventDisableTiming) == cudaSuccess)
              && (cudaEventCreateWithFlags(&eJoin, cudaEventDisableTiming) == cudaSuccess)
              && (cudaEventCreateWithFlags(&eCsr,  cudaEventDisableTiming) == cudaSuccess);
    }
    cudaStream_t sy = forked ? sY : 0;
    cudaStream_t sc = forked ? sC : 0;
    if (forked) {
        cudaEventRecord(eFork, 0);
        cudaStreamWaitEvent(sY, eFork, 0);
        cudaStreamWaitEvent(sC, eFork, 0);
    }

    // ----- X CSR build (side stream sc) -----
    build_csr(mm, E_MM, M_NODES, rpA, colA, curA, degA, sc);
    if (forked) cudaEventRecord(eCsr, sC);

    // ----- X branch (stream 0) -----
    cudaMemsetAsync(xfh + (size_t)M_NODES * 64, 0,
                    (size_t)(MPAD - M_NODES) * 64 * sizeof(__half), 0);
    // GAT layer 1: projection with fused alpha
    cudaMemsetAsync(asrc, 0, M_NODES * 2 * sizeof(float), 0);
    cudaMemsetAsync(adst, 0, M_NODES * 2 * sizeof(float), 0);
    run_gemm(x_m, W_gx1, nullptr, h, M_NODES, 64, 256, 0, 0, 0,
             as_gx1, ad_gx1, asrc, adst, 2, 128);
    if (forked) cudaStreamWaitEvent(0, eCsr, 0);
    gat_aggregate<2, 4><<<(M_NODES * 2 + 7) / 8, 256, 0, 0>>>(rpA, colA, asrc, adst, h, b_gx1, feat, M_NODES);
    // GAT layer 2
    cudaMemsetAsync(asrc, 0, M_NODES * sizeof(float), 0);
    cudaMemsetAsync(adst, 0, M_NODES * sizeof(float), 0);
    run_gemm(feat, W_gx2, nullptr, h, M_NODES, 256, 64, 0, 0, 0,
             as_gx2, ad_gx2, asrc, adst, 1, 64);
    gat_aggregate<1, 2><<<(M_NODES + 7) / 8, 256, 0, 0>>>(rpA, colA, asrc, adst, h, b_gx2, X, M_NODES);
    // MLP
    run_gemm(X,  lx1_W, lx1_b, t1, M_NODES, 64,  256, 1, 0);
    run_gemm(t1, lx2_W, lx2_b, t2, M_NODES, 256, 128, 1, 0);
    run_gemm(t2, lx3_W, lx3_b, (float*)xfh, M_NODES, 128, 64, 1, 0, 1);

    // ----- Y branch (side stream sy) -----
    cudaMemsetAsync(yfh + (size_t)D_NODES * 64, 0,
                    (size_t)(DPAD - D_NODES) * 64 * sizeof(__half), sy);
    build_csr(dd, E_DD, D_NODES, rpB, colB, curB, degB, sy);
    cudaMemsetAsync(asrcY, 0, D_NODES * 2 * sizeof(float), sy);
    cudaMemsetAsync(adstY, 0, D_NODES * 2 * sizeof(float), sy);
    run_gemm(x_d, W_gy1, nullptr, hY, D_NODES, 64, 256, 0, sy, 0,
             as_gy1, ad_gy1, asrcY, adstY, 2, 128);
    gat_aggregate<2, 4><<<(D_NODES * 2 + 7) / 8, 256, 0, sy>>>(rpB, colB, asrcY, adstY, hY, b_gy1, featY, D_NODES);
    cudaMemsetAsync(asrcY, 0, D_NODES * sizeof(float), sy);
    cudaMemsetAsync(adstY, 0, D_NODES * sizeof(float), sy);
    run_gemm(featY, W_gy2, nullptr, hY, D_NODES, 256, 64, 0, sy, 0,
             as_gy2, ad_gy2, asrcY, adstY, 1, 64);
    gat_aggregate<1, 2><<<(D_NODES + 7) / 8, 256, 0, sy>>>(rpB, colB, asrcY, adstY, hY, b_gy2, XY, D_NODES);
    run_gemm(XY,  ly1_W, ly1_b, t1Y, D_NODES, 64,  256, 1, sy);
    run_gemm(t1Y, ly2_W, ly2_b, t2Y, D_NODES, 256, 128, 1, sy);
    run_gemm(t2Y, ly3_W, ly3_b, (float*)yfh, D_NODES, 128, 64, 1, sy, 1);

    if (forked) {
        cudaEventRecord(eJoin, sY);
        cudaStreamWaitEvent(0, eJoin, 0);
    }

    // ----- final: out = xf @ yf^T (fp16 operands, f32 accum/output) -----
    dim3 grid(DPAD / 128, MPAD / 128);   // 63 x 157
    final_mma_kernel<<<grid, 256, 0, 0>>>(xfh, yfh, (float*)d_out);
}

// round 16
// speedup vs baseline: 1.4258x; 1.0369x over previous
#include <cuda_runtime.h>
#include <cuda_fp16.h>
#include <math.h>
#include <stdint.h>

// ---------------- problem constants ----------------
#define M_NODES 20000
#define D_NODES 8000
#define E_MM    320000
#define E_DD    128000

#define MPAD 20096
#define DPAD 8064

// ---------------- scratch ----------------
__device__ __half  g_h   [M_NODES * 256];
__device__ float   g_feat[M_NODES * 256];
__device__ float   g_asrc[M_NODES * 2];
__device__ float   g_adst[M_NODES * 2];
__device__ float   g_X   [M_NODES * 64];
__device__ float   g_t1  [M_NODES * 256];
__device__ float   g_t2  [M_NODES * 128];
__device__ __half  g_xfh [MPAD * 64];
__device__ int     g_rpA [M_NODES + 1];
__device__ int     g_colA[E_MM];
__device__ int     g_curA[M_NODES];
__device__ int     g_degA[M_NODES];
__device__ __half  g_hY   [D_NODES * 256];
__device__ float   g_featY[D_NODES * 256];
__device__ float   g_asrcY[D_NODES * 2];
__device__ float   g_adstY[D_NODES * 2];
__device__ float   g_XY   [D_NODES * 64];
__device__ float   g_t1Y  [D_NODES * 256];
__device__ float   g_t2Y  [D_NODES * 128];
__device__ __half  g_yfh  [DPAD * 64];
__device__ int     g_rpB  [D_NODES + 1];
__device__ int     g_colB [E_DD];
__device__ int     g_curB [D_NODES];
__device__ int     g_degB [D_NODES];

// ---------------- helpers ----------------
__device__ __forceinline__ uint32_t cvt_tf32(float f) {
    uint32_t r;
    asm("cvt.rna.tf32.f32 %0, %1;" : "=r"(r) : "f"(f));
    return r;
}
__device__ __forceinline__ void mma_tf32(float* d, const uint32_t* a, const uint32_t* b)
{
    asm volatile(
        "mma.sync.aligned.m16n8k8.row.col.f32.tf32.tf32.f32 "
        "{%0,%1,%2,%3}, {%4,%5,%6,%7}, {%8,%9}, {%0,%1,%2,%3};"
        : "+f"(d[0]), "+f"(d[1]), "+f"(d[2]), "+f"(d[3])
        : "r"(a[0]), "r"(a[1]), "r"(a[2]), "r"(a[3]), "r"(b[0]), "r"(b[1]));
}
__device__ __forceinline__ void mma_f16(float* d, const uint32_t* a, const uint32_t* b)
{
    asm volatile(
        "mma.sync.aligned.m16n8k16.row.col.f32.f16.f16.f32 "
        "{%0,%1,%2,%3}, {%4,%5,%6,%7}, {%8,%9}, {%0,%1,%2,%3};"
        : "+f"(d[0]), "+f"(d[1]), "+f"(d[2]), "+f"(d[3])
        : "r"(a[0]), "r"(a[1]), "r"(a[2]), "r"(a[3]), "r"(b[0]), "r"(b[1]));
}

// ============ generic tf32 mma GEMM (128x64 tile) ==========================
// Optional fused alpha: per-row dots of the f32 output tile against
// a_src/a_dst, warp-reduced over t-lanes, atomically accumulated.
#define GSTR 68
__global__ void __launch_bounds__(256) mma_gemm_kernel(
    const float* __restrict__ A, const float* __restrict__ B,
    const float* __restrict__ bias, float* __restrict__ C,
    int N, int K, int Cn, int relu_act, int out_half,
    const float* __restrict__ a_s, const float* __restrict__ a_d,
    float* __restrict__ asrc, float* __restrict__ adst, int H, int Chead)
{
    __shared__ uint32_t As[128 * GSTR];
    __shared__ uint32_t Bs[64 * GSTR];

    const int tid = threadIdx.x, wid = tid >> 5, lane = tid & 31;
    const int g = lane >> 2, t = lane & 3;
    const int wm = wid & 3, wn = wid >> 2;
    const int row0 = blockIdx.y * 128, col0 = blockIdx.x * 64;

    float acc[2][4][4];
    #pragma unroll
    for (int i = 0; i < 2; i++)
        #pragma unroll
        for (int j = 0; j < 4; j++)
            #pragma unroll
            for (int q = 0; q < 4; q++) acc[i][j][q] = 0.f;

    for (int k0 = 0; k0 < K; k0 += 64) {
        #pragma unroll
        for (int i = tid; i < 2048; i += 256) {
            int row = i >> 4, c4 = (i & 15) << 2;
            int gm = row0 + row;
            float4 v = make_float4(0.f, 0.f, 0.f, 0.f);
            if (gm < N) v = *(const float4*)(A + (size_t)gm * K + k0 + c4);
            uint32_t* p = &As[row * GSTR + c4];
            p[0] = cvt_tf32(v.x); p[1] = cvt_tf32(v.y);
            p[2] = cvt_tf32(v.z); p[3] = cvt_tf32(v.w);
        }
        #pragma unroll
        for (int i = tid; i < 1024; i += 256) {
            int kk = i >> 4, c4 = (i & 15) << 2;
            float4 v = *(const float4*)(B + (size_t)(k0 + kk) * Cn + col0 + c4);
            Bs[(c4 + 0) * GSTR + kk] = cvt_tf32(v.x);
            Bs[(c4 + 1) * GSTR + kk] = cvt_tf32(v.y);
            Bs[(c4 + 2) * GSTR + kk] = cvt_tf32(v.z);
            Bs[(c4 + 3) * GSTR + kk] = cvt_tf32(v.w);
        }
        __syncthreads();

        #pragma unroll
        for (int ks = 0; ks < 8; ks++) {
            const int kb = ks * 8;
            uint32_t a[2][4];
            #pragma unroll
            for (int mf = 0; mf < 2; mf++) {
                int r = wm * 32 + mf * 16;
                a[mf][0] = As[(r + g)     * GSTR + kb + t];
                a[mf][1] = As[(r + g + 8) * GSTR + kb + t];
                a[mf][2] = As[(r + g)     * GSTR + kb + t + 4];
                a[mf][3] = As[(r + g + 8) * GSTR + kb + t + 4];
            }
            #pragma unroll
            for (int nf = 0; nf < 4; nf++) {
                uint32_t b[2];
                int n = wn * 32 + nf * 8 + g;
                b[0] = Bs[n * GSTR + kb + t];
                b[1] = Bs[n * GSTR + kb + t + 4];
                mma_tf32(acc[0][nf], a[0], b);
                mma_tf32(acc[1][nf], a[1], b);
            }
        }
        __syncthreads();
    }

    const int head = (a_s != nullptr) ? (col0 / Chead) : 0;

    #pragma unroll
    for (int mf = 0; mf < 2; mf++) {
        #pragma unroll
        for (int rr = 0; rr < 2; rr++) {
            int row = row0 + wm * 32 + mf * 16 + rr * 8 + g;
            bool valid = (row < N);
            float s1 = 0.f, s2 = 0.f;
            #pragma unroll
            for (int nf = 0; nf < 4; nf++) {
                int col = col0 + wn * 32 + nf * 8 + 2 * t;
                float2 v;
                v.x = acc[mf][nf][rr * 2 + 0];
                v.y = acc[mf][nf][rr * 2 + 1];
                if (a_s) {
                    int c = col - head * Chead;
                    const float* asp = a_s + head * Chead;
                    const float* adp = a_d + head * Chead;
                    s1 += v.x * asp[c] + v.y * asp[c + 1];
                    s2 += v.x * adp[c] + v.y * adp[c + 1];
                }
                if (valid) {
                    if (bias) { v.x += bias[col]; v.y += bias[col + 1]; }
                    if (relu_act) { v.x = fmaxf(v.x, 0.f); v.y = fmaxf(v.y, 0.f); }
                    if (out_half) {
                        __half2 hv = __float22half2_rn(v);
                        *(__half2*)((__half*)C + (size_t)row * Cn + col) = hv;
                    } else {
                        *(float2*)(C + (size_t)row * Cn + col) = v;
                    }
                }
            }
            if (a_s) {
                // reduce over the 4 t-lanes sharing this row (lanes g*4+t)
                s1 += __shfl_xor_sync(~0u, s1, 1);
                s1 += __shfl_xor_sync(~0u, s1, 2);
                s2 += __shfl_xor_sync(~0u, s2, 1);
                s2 += __shfl_xor_sync(~0u, s2, 2);
                if (t == 0 && valid) {
                    atomicAdd(&asrc[row * H + head], s1);
                    atomicAdd(&adst[row * H + head], s2);
                }
            }
        }
    }
}

// ---------------- CSR build ----------------
__global__ void hist_kernel(const int* __restrict__ dst, int* __restrict__ deg, int E)
{
    int i = blockIdx.x * blockDim.x + threadIdx.x;
    if (i < E) atomicAdd(&deg[dst[i]], 1);
}

__global__ void __launch_bounds__(1024) scan_kernel(const int* __restrict__ deg,
                                                    int* __restrict__ rowptr,
                                                    int* __restrict__ cursor, int N)
{
    __shared__ int sums[32];
    __shared__ int carry;
    int tid = threadIdx.x;
    if (tid == 0) carry = 0;
    __syncthreads();
    for (int base = 0; base < N; base += 1024) {
        int i = base + tid;
        int v = (i < N) ? deg[i] : 0;
        int x = v;
        #pragma unroll
        for (int o = 1; o < 32; o <<= 1) {
            int y = __shfl_up_sync(~0u, x, o);
            if ((tid & 31) >= o) x += y;
        }
        if ((tid & 31) == 31) sums[tid >> 5] = x;
        __syncthreads();
        if (tid < 32) {
            int s = sums[tid];
            #pragma unroll
            for (int o = 1; o < 32; o <<= 1) {
                int y = __shfl_up_sync(~0u, s, o);
                if (tid >= o) s += y;
            }
            sums[tid] = s;
        }
        __syncthreads();
        int incl = x + ((tid >= 32) ? sums[(tid >> 5) - 1] : 0) + carry;
        if (i < N) {
            rowptr[i + 1] = incl;
            cursor[i] = incl - v;
        }
        __syncthreads();
        if (tid == 1023) carry = incl;
        __syncthreads();
    }
    if (tid == 0) rowptr[0] = 0;
}

__global__ void scatter_kernel(const int* __restrict__ src, const int* __restrict__ dst,
                               int* __restrict__ cursor, int* __restrict__ col, int E)
{
    int i = blockIdx.x * blockDim.x + threadIdx.x;
    if (i >= E) return;
    int slot = atomicAdd(&cursor[dst[i]], 1);
    col[slot] = src[i];
}

// ---------------- GAT aggregate (fp16 h) ----------------
template<int H, int CPL>
__global__ void gat_aggregate(const int* __restrict__ rowptr, const int* __restrict__ col,
                              const float* __restrict__ asrc, const float* __restrict__ adst,
                              const __half* __restrict__ h, const float* __restrict__ bias,
                              float* __restrict__ out, int N)
{
    const int C = 32 * CPL;
    int warp = (blockIdx.x * blockDim.x + threadIdx.x) >> 5;
    int lane = threadIdx.x & 31;
    if (warp >= N * H) return;
    int d = warp / H, hh = warp % H;
    int beg = rowptr[d], end = rowptr[d + 1];
    float ad = adst[d * H + hh];

    float m = -INFINITY, den = 0.f;
    for (int i = beg + lane; i < end; i += 32) {
        float v = asrc[col[i] * H + hh] + ad;
        v = (v >= 0.f) ? v : 0.2f * v;
        if (v > m) { den = den * __expf(m - v) + 1.f; m = v; }
        else den += __expf(v - m);
    }
    #pragma unroll
    for (int o = 16; o; o >>= 1) {
        float m2 = __shfl_xor_sync(~0u, m, o);
        float d2 = __shfl_xor_sync(~0u, den, o);
        float nm = fmaxf(m, m2);
        float f1 = (m == nm) ? 1.f : __expf(m - nm);
        float f2 = (m2 == nm) ? 1.f : __expf(m2 - nm);
        den = den * f1 + d2 * f2;
        m = nm;
    }
    float inv = 1.f / (den + 1e-16f);

    float acc[CPL];
    #pragma unroll
    for (int q = 0; q < CPL; q++) acc[q] = 0.f;

    for (int base = beg; base < end; base += 32) {
        int i = base + lane;
        int s = 0; float coef = 0.f;
        if (i < end) {
            s = col[i];
            float v = asrc[s * H + hh] + ad;
            v = (v >= 0.f) ? v : 0.2f * v;
            coef = __expf(v - m) * inv;
        }
        int cnt = min(32, end - base);
        for (int j = 0; j < cnt; j++) {
            int sj = __shfl_sync(~0u, s, j);
            float cj = __shfl_sync(~0u, coef, j);
            const __half* hp = h + ((size_t)sj * H + hh) * C + lane * CPL;
            if (CPL == 4) {
                uint2 raw = *(const uint2*)hp;
                float2 p0 = __half22float2(*(const __half2*)&raw.x);
                float2 p1 = __half22float2(*(const __half2*)&raw.y);
                acc[0] += cj * p0.x; acc[1] += cj * p0.y;
                acc[2] += cj * p1.x; acc[3] += cj * p1.y;
            } else {
                uint32_t raw = *(const uint32_t*)hp;
                float2 p0 = __half22float2(*(const __half2*)&raw);
                acc[0] += cj * p0.x; acc[1] += cj * p0.y;
            }
        }
    }

    float* op = out + ((size_t)d * H + hh) * C + lane * CPL;
    const float* bp = bias + hh * C + lane * CPL;
    if (CPL == 4) {
        float4 v;
        v.x = fmaxf(acc[0] + bp[0], 0.f); v.y = fmaxf(acc[1] + bp[1], 0.f);
        v.z = fmaxf(acc[2] + bp[2], 0.f); v.w = fmaxf(acc[3] + bp[3], 0.f);
        *(float4*)op = v;
    } else {
        float2 v;
        v.x = fmaxf(acc[0] + bp[0], 0.f); v.y = fmaxf(acc[1] + bp[1], 0.f);
        *(float2*)op = v;
    }
}

// ================= final GEMM: out = xf @ yf^T (fp16 m16n8k16) =============
#define BSTR 72
__global__ void __launch_bounds__(256) final_mma_kernel(
    const __half* __restrict__ A, const __half* __restrict__ B, float* __restrict__ C)
{
    __shared__ __half As[128 * BSTR];
    __shared__ __half Bs[128 * BSTR];

    const int tid = threadIdx.x, wid = tid >> 5, lane = tid & 31;
    const int g = lane >> 2, t = lane & 3;
    const int wm = wid & 3, wn = wid >> 2;
    const int m0 = blockIdx.y * 128, n0 = blockIdx.x * 128;

    {
        const __half* Ag = A + (size_t)m0 * 64;
        const __half* Bg = B + (size_t)n0 * 64;
        #pragma unroll
        for (int i = tid; i < 1024; i += 256) {
            int row = i >> 3, c8 = (i & 7) << 3;
            uint4 v = *(const uint4*)(Ag + (size_t)row * 64 + c8);
            *(uint4*)&As[row * BSTR + c8] = v;
        }
        #pragma unroll
        for (int i = tid; i < 1024; i += 256) {
            int row = i >> 3, c8 = (i & 7) << 3;
            uint4 v = *(const uint4*)(Bg + (size_t)row * 64 + c8);
            *(uint4*)&Bs[row * BSTR + c8] = v;
        }
    }
    __syncthreads();

    float acc[2][8][4];
    #pragma unroll
    for (int i = 0; i < 2; i++)
        #pragma unroll
        for (int j = 0; j < 8; j++)
            #pragma unroll
            for (int q = 0; q < 4; q++) acc[i][j][q] = 0.f;

    #pragma unroll
    for (int ks = 0; ks < 4; ks++) {
        const int kb = ks * 16;
        uint32_t a[2][4];
        #pragma unroll
        for (int mf = 0; mf < 2; mf++) {
            int r = wm * 32 + mf * 16;
            a[mf][0] = *(const uint32_t*)&As[(r + g)     * BSTR + kb + 2 * t];
            a[mf][1] = *(const uint32_t*)&As[(r + g + 8) * BSTR + kb + 2 * t];
            a[mf][2] = *(const uint32_t*)&As[(r + g)     * BSTR + kb + 2 * t + 8];
            a[mf][3] = *(const uint32_t*)&As[(r + g + 8) * BSTR + kb + 2 * t + 8];
        }
        #pragma unroll
        for (int nf = 0; nf < 8; nf++) {
            int n = wn * 64 + nf * 8 + g;
            uint32_t b[2];
            b[0] = *(const uint32_t*)&Bs[n * BSTR + kb + 2 * t];
            b[1] = *(const uint32_t*)&Bs[n * BSTR + kb + 2 * t + 8];
            mma_f16(acc[0][nf], a[0], b);
            mma_f16(acc[1][nf], a[1], b);
        }
    }

    #pragma unroll
    for (int mf = 0; mf < 2; mf++) {
        #pragma unroll
        for (int rr = 0; rr < 2; rr++) {
            int row = m0 + wm * 32 + mf * 16 + rr * 8 + g;
            if (row >= M_NODES) continue;
            float* cp = C + (size_t)row * D_NODES;
            #pragma unroll
            for (int nf = 0; nf < 8; nf++) {
                int col = n0 + wn * 64 + nf * 8 + 2 * t;
                if (col < D_NODES) {
                    float2 v;
                    v.x = acc[mf][nf][rr * 2 + 0];
                    v.y = acc[mf][nf][rr * 2 + 1];
                    *(float2*)(cp + col) = v;
                }
            }
        }
    }
}

// ---------------- host orchestration ----------------
static void run_gemm(const float* A, const float* B, const float* bias, float* C,
                     int N, int K, int Cn, int act, cudaStream_t st, int out_half = 0,
                     const float* a_s = nullptr, const float* a_d = nullptr,
                     float* asrc = nullptr, float* adst = nullptr,
                     int H = 1, int Chead = 64)
{
    dim3 g(Cn / 64, (N + 127) / 128);
    mma_gemm_kernel<<<g, 256, 0, st>>>(A, B, bias, C, N, K, Cn, act, out_half,
                                       a_s, a_d, asrc, adst, H, Chead);
}

static void build_csr(const int* ei, int E, int N, int* rowptr, int* col,
                      int* cursor, int* deg, cudaStream_t st)
{
    const int* src = ei;
    const int* dst = ei + E;
    cudaMemsetAsync(deg, 0, N * sizeof(int), st);
    hist_kernel<<<(E + 255) / 256, 256, 0, st>>>(dst, deg, E);
    scan_kernel<<<1, 1024, 0, st>>>(deg, rowptr, cursor, N);
    scatter_kernel<<<(E + 255) / 256, 256, 0, st>>>(src, dst, cursor, col, E);
}

extern "C" void kernel_launch(void* const* d_in, const int* in_sizes, int n_in,
                              void* d_out, int out_size)
{
    const float* x_m  = (const float*)d_in[0];
    const float* x_d  = (const float*)d_in[1];
    const int*   mm   = (const int*)d_in[2];
    const int*   dd   = (const int*)d_in[3];
    const float* W_gx1 = (const float*)d_in[4];
    const float* as_gx1 = (const float*)d_in[5];
    const float* ad_gx1 = (const float*)d_in[6];
    const float* b_gx1  = (const float*)d_in[7];
    const float* W_gx2 = (const float*)d_in[8];
    const float* as_gx2 = (const float*)d_in[9];
    const float* ad_gx2 = (const float*)d_in[10];
    const float* b_gx2  = (const float*)d_in[11];
    const float* W_gy1 = (const float*)d_in[12];
    const float* as_gy1 = (const float*)d_in[13];
    const float* ad_gy1 = (const float*)d_in[14];
    const float* b_gy1  = (const float*)d_in[15];
    const float* W_gy2 = (const float*)d_in[16];
    const float* as_gy2 = (const float*)d_in[17];
    const float* ad_gy2 = (const float*)d_in[18];
    const float* b_gy2  = (const float*)d_in[19];
    const float* lx1_W = (const float*)d_in[20];
    const float* lx1_b = (const float*)d_in[21];
    const float* lx2_W = (const float*)d_in[22];
    const float* lx2_b = (const float*)d_in[23];
    const float* lx3_W = (const float*)d_in[24];
    const float* lx3_b = (const float*)d_in[25];
    const float* ly1_W = (const float*)d_in[26];
    const float* ly1_b = (const float*)d_in[27];
    const float* ly2_W = (const float*)d_in[28];
    const float* ly2_b = (const float*)d_in[29];
    const float* ly3_W = (const float*)d_in[30];
    const float* ly3_b = (const float*)d_in[31];

    float *feat, *asrc, *adst, *X, *t1, *t2;
    float *featY, *asrcY, *adstY, *XY, *t1Y, *t2Y;
    __half *h, *hY, *xfh, *yfh;
    int *rpA, *colA, *curA, *degA, *rpB, *colB, *curB, *degB;
    cudaGetSymbolAddress((void**)&h,    g_h);
    cudaGetSymbolAddress((void**)&feat, g_feat);
    cudaGetSymbolAddress((void**)&asrc, g_asrc);
    cudaGetSymbolAddress((void**)&adst, g_adst);
    cudaGetSymbolAddress((void**)&X,    g_X);
    cudaGetSymbolAddress((void**)&t1,   g_t1);
    cudaGetSymbolAddress((void**)&t2,   g_t2);
    cudaGetSymbolAddress((void**)&xfh,  g_xfh);
    cudaGetSymbolAddress((void**)&rpA,  g_rpA);
    cudaGetSymbolAddress((void**)&colA, g_colA);
    cudaGetSymbolAddress((void**)&curA, g_curA);
    cudaGetSymbolAddress((void**)&degA, g_degA);
    cudaGetSymbolAddress((void**)&hY,    g_hY);
    cudaGetSymbolAddress((void**)&featY, g_featY);
    cudaGetSymbolAddress((void**)&asrcY, g_asrcY);
    cudaGetSymbolAddress((void**)&adstY, g_adstY);
    cudaGetSymbolAddress((void**)&XY,    g_XY);
    cudaGetSymbolAddress((void**)&t1Y,   g_t1Y);
    cudaGetSymbolAddress((void**)&t2Y,   g_t2Y);
    cudaGetSymbolAddress((void**)&yfh,   g_yfh);
    cudaGetSymbolAddress((void**)&rpB,  g_rpB);
    cudaGetSymbolAddress((void**)&colB, g_colB);
    cudaGetSymbolAddress((void**)&curB, g_curB);
    cudaGetSymbolAddress((void**)&degB, g_degB);

    static cudaStream_t sY = 0, sC = 0;
    static cudaEvent_t eFork = 0, eJoin = 0, eCsr = 0;
    static bool inited = false, forked = false;
    if (!inited) {
        inited = true;
        forked = (cudaStreamCreateWithFlags(&sY, cudaStreamNonBlocking) == cudaSuccess)
              && (cudaStreamCreateWithFlags(&sC, cudaStreamNonBlocking) == cudaSuccess)
              && (cudaEventCreateWithFlags(&eFork, cudaEventDisableTiming) == cudaSuccess)
              && (cudaEventCreateWithFlags(&eJoin, cudaEventDisableTiming) == cudaSuccess)
              && (cudaEventCreateWithFlags(&eCsr,  cudaEventDisableTiming) == cudaSuccess);
    }
    cudaStream_t sy = forked ? sY : 0;
    cudaStream_t sc = forked ? sC : 0;
    if (forked) {
        cudaEventRecord(eFork, 0);
        cudaStreamWaitEvent(sY, eFork, 0);
        cudaStreamWaitEvent(sC, eFork, 0);
    }

    // ----- X CSR build (side stream sc) -----
    build_csr(mm, E_MM, M_NODES, rpA, colA, curA, degA, sc);
    if (forked) cudaEventRecord(eCsr, sC);

    // ----- X branch (stream 0) -----
    cudaMemsetAsync(xfh + (size_t)M_NODES * 64, 0,
                    (size_t)(MPAD - M_NODES) * 64 * sizeof(__half), 0);
    cudaMemsetAsync(asrc, 0, M_NODES * 2 * sizeof(float), 0);
    cudaMemsetAsync(adst, 0, M_NODES * 2 * sizeof(float), 0);
    run_gemm(x_m, W_gx1, nullptr, (float*)h, M_NODES, 64, 256, 0, 0, 1,
             as_gx1, ad_gx1, asrc, adst, 2, 128);
    if (forked) cudaStreamWaitEvent(0, eCsr, 0);
    gat_aggregate<2, 4><<<(M_NODES * 2 + 7) / 8, 256, 0, 0>>>(rpA, colA, asrc, adst, h, b_gx1, feat, M_NODES);
    cudaMemsetAsync(asrc, 0, M_NODES * sizeof(float), 0);
    cudaMemsetAsync(adst, 0, M_NODES * sizeof(float), 0);
    run_gemm(feat, W_gx2, nullptr, (float*)h, M_NODES, 256, 64, 0, 0, 1,
             as_gx2, ad_gx2, asrc, adst, 1, 64);
    gat_aggregate<1, 2><<<(M_NODES + 7) / 8, 256, 0, 0>>>(rpA, colA, asrc, adst, h, b_gx2, X, M_NODES);
    run_gemm(X,  lx1_W, lx1_b, t1, M_NODES, 64,  256, 1, 0);
    run_gemm(t1, lx2_W, lx2_b, t2, M_NODES, 256, 128, 1, 0);
    run_gemm(t2, lx3_W, lx3_b, (float*)xfh, M_NODES, 128, 64, 1, 0, 1);

    // ----- Y branch (side stream sy) -----
    cudaMemsetAsync(yfh + (size_t)D_NODES * 64, 0,
                    (size_t)(DPAD - D_NODES) * 64 * sizeof(__half), sy);
    build_csr(dd, E_DD, D_NODES, rpB, colB, curB, degB, sy);
    cudaMemsetAsync(asrcY, 0, D_NODES * 2 * sizeof(float), sy);
    cudaMemsetAsync(adstY, 0, D_NODES * 2 * sizeof(float), sy);
    run_gemm(x_d, W_gy1, nullptr, (float*)hY, D_NODES, 64, 256, 0, sy, 1,
             as_gy1, ad_gy1, asrcY, adstY, 2, 128);
    gat_aggregate<2, 4><<<(D_NODES * 2 + 7) / 8, 256, 0, sy>>>(rpB, colB, asrcY, adstY, hY, b_gy1, featY, D_NODES);
    cudaMemsetAsync(asrcY, 0, D_NODES * sizeof(float), sy);
    cudaMemsetAsync(adstY, 0, D_NODES * sizeof(float), sy);
    run_gemm(featY, W_gy2, nullptr, (float*)hY, D_NODES, 256, 64, 0, sy, 1,
             as_gy2, ad_gy2, asrcY, adstY, 1, 64);
    gat_aggregate<1, 2><<<(D_NODES + 7) / 8, 256, 0, sy>>>(rpB, colB, asrcY, adstY, hY, b_gy2, XY, D_NODES);
    run_gemm(XY,  ly1_W, ly1_b, t1Y, D_NODES, 64,  256, 1, sy);
    run_gemm(t1Y, ly2_W, ly2_b, t2Y, D_NODES, 256, 128, 1, sy);
    run_gemm(t2Y, ly3_W, ly3_b, (float*)yfh, D_NODES, 128, 64, 1, sy, 1);

    if (forked) {
        cudaEventRecord(eJoin, sY);
        cudaStreamWaitEvent(0, eJoin, 0);
    }

    // ----- final: out = xf @ yf^T (fp16 operands, f32 accum/output) -----
    dim3 grid(DPAD / 128, MPAD / 128);   // 63 x 157
    final_mma_kernel<<<grid, 256, 0, 0>>>(xfh, yfh, (float*)d_out);
}

// round 17
// speedup vs baseline: 1.4878x; 1.0435x over previous
#include <cuda_runtime.h>
#include <cuda_fp16.h>
#include <math.h>
#include <stdint.h>

// ---------------- problem constants ----------------
#define M_NODES 20000
#define D_NODES 8000
#define E_MM    320000
#define E_DD    128000

#define MPAD 20096
#define DPAD 8064

// ---------------- scratch ----------------
__device__ __half  g_h   [M_NODES * 256];
__device__ float   g_feat[M_NODES * 256];
__device__ float   g_asrc[M_NODES * 2];
__device__ float   g_adst[M_NODES * 2];
__device__ __half  g_X   [M_NODES * 64];
__device__ __half  g_t1  [M_NODES * 256];
__device__ __half  g_t2  [M_NODES * 128];
__device__ __half  g_xfh [MPAD * 64];
__device__ int     g_rpA [M_NODES + 1];
__device__ int     g_colA[E_MM];
__device__ int     g_curA[M_NODES];
__device__ int     g_degA[M_NODES];
__device__ __half  g_hY   [D_NODES * 256];
__device__ float   g_featY[D_NODES * 256];
__device__ float   g_asrcY[D_NODES * 2];
__device__ float   g_adstY[D_NODES * 2];
__device__ __half  g_XY   [D_NODES * 64];
__device__ __half  g_t1Y  [D_NODES * 256];
__device__ __half  g_t2Y  [D_NODES * 128];
__device__ __half  g_yfh  [DPAD * 64];
__device__ int     g_rpB  [D_NODES + 1];
__device__ int     g_colB [E_DD];
__device__ int     g_curB [D_NODES];
__device__ int     g_degB [D_NODES];

// ---------------- helpers ----------------
__device__ __forceinline__ uint32_t cvt_tf32(float f) {
    uint32_t r;
    asm("cvt.rna.tf32.f32 %0, %1;" : "=r"(r) : "f"(f));
    return r;
}
__device__ __forceinline__ void mma_tf32(float* d, const uint32_t* a, const uint32_t* b)
{
    asm volatile(
        "mma.sync.aligned.m16n8k8.row.col.f32.tf32.tf32.f32 "
        "{%0,%1,%2,%3}, {%4,%5,%6,%7}, {%8,%9}, {%0,%1,%2,%3};"
        : "+f"(d[0]), "+f"(d[1]), "+f"(d[2]), "+f"(d[3])
        : "r"(a[0]), "r"(a[1]), "r"(a[2]), "r"(a[3]), "r"(b[0]), "r"(b[1]));
}
__device__ __forceinline__ void mma_f16(float* d, const uint32_t* a, const uint32_t* b)
{
    asm volatile(
        "mma.sync.aligned.m16n8k16.row.col.f32.f16.f16.f32 "
        "{%0,%1,%2,%3}, {%4,%5,%6,%7}, {%8,%9}, {%0,%1,%2,%3};"
        : "+f"(d[0]), "+f"(d[1]), "+f"(d[2]), "+f"(d[3])
        : "r"(a[0]), "r"(a[1]), "r"(a[2]), "r"(a[3]), "r"(b[0]), "r"(b[1]));
}

// ============ tf32 mma GEMM (128x64 tile), used for GAT projections ========
#define GSTR 68
__global__ void __launch_bounds__(256) mma_gemm_kernel(
    const float* __restrict__ A, const float* __restrict__ B,
    const float* __restrict__ bias, float* __restrict__ C,
    int N, int K, int Cn, int relu_act, int out_half,
    const float* __restrict__ a_s, const float* __restrict__ a_d,
    float* __restrict__ asrc, float* __restrict__ adst, int H, int Chead)
{
    __shared__ uint32_t As[128 * GSTR];
    __shared__ uint32_t Bs[64 * GSTR];

    const int tid = threadIdx.x, wid = tid >> 5, lane = tid & 31;
    const int g = lane >> 2, t = lane & 3;
    const int wm = wid & 3, wn = wid >> 2;
    const int row0 = blockIdx.y * 128, col0 = blockIdx.x * 64;

    float acc[2][4][4];
    #pragma unroll
    for (int i = 0; i < 2; i++)
        #pragma unroll
        for (int j = 0; j < 4; j++)
            #pragma unroll
            for (int q = 0; q < 4; q++) acc[i][j][q] = 0.f;

    for (int k0 = 0; k0 < K; k0 += 64) {
        #pragma unroll
        for (int i = tid; i < 2048; i += 256) {
            int row = i >> 4, c4 = (i & 15) << 2;
            int gm = row0 + row;
            float4 v = make_float4(0.f, 0.f, 0.f, 0.f);
            if (gm < N) v = *(const float4*)(A + (size_t)gm * K + k0 + c4);
            uint32_t* p = &As[row * GSTR + c4];
            p[0] = cvt_tf32(v.x); p[1] = cvt_tf32(v.y);
            p[2] = cvt_tf32(v.z); p[3] = cvt_tf32(v.w);
        }
        #pragma unroll
        for (int i = tid; i < 1024; i += 256) {
            int kk = i >> 4, c4 = (i & 15) << 2;
            float4 v = *(const float4*)(B + (size_t)(k0 + kk) * Cn + col0 + c4);
            Bs[(c4 + 0) * GSTR + kk] = cvt_tf32(v.x);
            Bs[(c4 + 1) * GSTR + kk] = cvt_tf32(v.y);
            Bs[(c4 + 2) * GSTR + kk] = cvt_tf32(v.z);
            Bs[(c4 + 3) * GSTR + kk] = cvt_tf32(v.w);
        }
        __syncthreads();

        #pragma unroll
        for (int ks = 0; ks < 8; ks++) {
            const int kb = ks * 8;
            uint32_t a[2][4];
            #pragma unroll
            for (int mf = 0; mf < 2; mf++) {
                int r = wm * 32 + mf * 16;
                a[mf][0] = As[(r + g)     * GSTR + kb + t];
                a[mf][1] = As[(r + g + 8) * GSTR + kb + t];
                a[mf][2] = As[(r + g)     * GSTR + kb + t + 4];
                a[mf][3] = As[(r + g + 8) * GSTR + kb + t + 4];
            }
            #pragma unroll
            for (int nf = 0; nf < 4; nf++) {
                uint32_t b[2];
                int n = wn * 32 + nf * 8 + g;
                b[0] = Bs[n * GSTR + kb + t];
                b[1] = Bs[n * GSTR + kb + t + 4];
                mma_tf32(acc[0][nf], a[0], b);
                mma_tf32(acc[1][nf], a[1], b);
            }
        }
        __syncthreads();
    }

    const int head = (a_s != nullptr) ? (col0 / Chead) : 0;

    #pragma unroll
    for (int mf = 0; mf < 2; mf++) {
        #pragma unroll
        for (int rr = 0; rr < 2; rr++) {
            int row = row0 + wm * 32 + mf * 16 + rr * 8 + g;
            bool valid = (row < N);
            float s1 = 0.f, s2 = 0.f;
            #pragma unroll
            for (int nf = 0; nf < 4; nf++) {
                int col = col0 + wn * 32 + nf * 8 + 2 * t;
                float2 v;
                v.x = acc[mf][nf][rr * 2 + 0];
                v.y = acc[mf][nf][rr * 2 + 1];
                if (a_s) {
                    int c = col - head * Chead;
                    const float* asp = a_s + head * Chead;
                    const float* adp = a_d + head * Chead;
                    s1 += v.x * asp[c] + v.y * asp[c + 1];
                    s2 += v.x * adp[c] + v.y * adp[c + 1];
                }
                if (valid) {
                    if (bias) { v.x += bias[col]; v.y += bias[col + 1]; }
                    if (relu_act) { v.x = fmaxf(v.x, 0.f); v.y = fmaxf(v.y, 0.f); }
                    if (out_half) {
                        __half2 hv = __float22half2_rn(v);
                        *(__half2*)((__half*)C + (size_t)row * Cn + col) = hv;
                    } else {
                        *(float2*)(C + (size_t)row * Cn + col) = v;
                    }
                }
            }
            if (a_s) {
                s1 += __shfl_xor_sync(~0u, s1, 1);
                s1 += __shfl_xor_sync(~0u, s1, 2);
                s2 += __shfl_xor_sync(~0u, s2, 1);
                s2 += __shfl_xor_sync(~0u, s2, 2);
                if (t == 0 && valid) {
                    atomicAdd(&asrc[row * H + head], s1);
                    atomicAdd(&adst[row * H + head], s2);
                }
            }
        }
    }
}

// ============ fp16 GEMM (128x64 tile): C_h = relu(A_h @ B_f32 + bias) ======
// A fp16 [N,K]; B f32 [K,Cn] converted to fp16 in staging; out fp16.
#define HSTR 72
__global__ void __launch_bounds__(256) hgemm_kernel(
    const __half* __restrict__ A, const float* __restrict__ B,
    const float* __restrict__ bias, __half* __restrict__ C,
    int N, int K, int Cn, int relu_act)
{
    __shared__ __half As[128 * HSTR];
    __shared__ __half Bs[64 * HSTR];

    const int tid = threadIdx.x, wid = tid >> 5, lane = tid & 31;
    const int g = lane >> 2, t = lane & 3;
    const int wm = wid & 3, wn = wid >> 2;
    const int row0 = blockIdx.y * 128, col0 = blockIdx.x * 64;

    float acc[2][4][4];
    #pragma unroll
    for (int i = 0; i < 2; i++)
        #pragma unroll
        for (int j = 0; j < 4; j++)
            #pragma unroll
            for (int q = 0; q < 4; q++) acc[i][j][q] = 0.f;

    for (int k0 = 0; k0 < K; k0 += 64) {
        // A chunk: 128 rows x 64 halfs (8x uint4 per row)
        #pragma unroll
        for (int i = tid; i < 1024; i += 256) {
            int row = i >> 3, c8 = (i & 7) << 3;
            int gm = row0 + row;
            uint4 v = make_uint4(0, 0, 0, 0);
            if (gm < N) v = *(const uint4*)(A + (size_t)gm * K + k0 + c8);
            *(uint4*)&As[row * HSTR + c8] = v;
        }
        // B chunk: [64 k x 64 cols] f32, coalesced load, transposed fp16 store
        #pragma unroll
        for (int i = tid; i < 1024; i += 256) {
            int kk = i >> 4, c4 = (i & 15) << 2;
            float4 v = *(const float4*)(B + (size_t)(k0 + kk) * Cn + col0 + c4);
            Bs[(c4 + 0) * HSTR + kk] = __float2half_rn(v.x);
            Bs[(c4 + 1) * HSTR + kk] = __float2half_rn(v.y);
            Bs[(c4 + 2) * HSTR + kk] = __float2half_rn(v.z);
            Bs[(c4 + 3) * HSTR + kk] = __float2half_rn(v.w);
        }
        __syncthreads();

        #pragma unroll
        for (int ks = 0; ks < 4; ks++) {
            const int kb = ks * 16;
            uint32_t a[2][4];
            #pragma unroll
            for (int mf = 0; mf < 2; mf++) {
                int r = wm * 32 + mf * 16;
                a[mf][0] = *(const uint32_t*)&As[(r + g)     * HSTR + kb + 2 * t];
                a[mf][1] = *(const uint32_t*)&As[(r + g + 8) * HSTR + kb + 2 * t];
                a[mf][2] = *(const uint32_t*)&As[(r + g)     * HSTR + kb + 2 * t + 8];
                a[mf][3] = *(const uint32_t*)&As[(r + g + 8) * HSTR + kb + 2 * t + 8];
            }
            #pragma unroll
            for (int nf = 0; nf < 4; nf++) {
                int n = wn * 32 + nf * 8 + g;
                uint32_t b[2];
                b[0] = *(const uint32_t*)&Bs[n * HSTR + kb + 2 * t];
                b[1] = *(const uint32_t*)&Bs[n * HSTR + kb + 2 * t + 8];
                mma_f16(acc[0][nf], a[0], b);
                mma_f16(acc[1][nf], a[1], b);
            }
        }
        __syncthreads();
    }

    #pragma unroll
    for (int mf = 0; mf < 2; mf++) {
        #pragma unroll
        for (int rr = 0; rr < 2; rr++) {
            int row = row0 + wm * 32 + mf * 16 + rr * 8 + g;
            if (row >= N) continue;
            #pragma unroll
            for (int nf = 0; nf < 4; nf++) {
                int col = col0 + wn * 32 + nf * 8 + 2 * t;
                float2 v;
                v.x = acc[mf][nf][rr * 2 + 0];
                v.y = acc[mf][nf][rr * 2 + 1];
                if (bias) { v.x += bias[col]; v.y += bias[col + 1]; }
                if (relu_act) { v.x = fmaxf(v.x, 0.f); v.y = fmaxf(v.y, 0.f); }
                __half2 hv = __float22half2_rn(v);
                *(__half2*)(C + (size_t)row * Cn + col) = hv;
            }
        }
    }
}

// ---------------- CSR build ----------------
__global__ void hist_kernel(const int* __restrict__ dst, int* __restrict__ deg, int E)
{
    int i = blockIdx.x * blockDim.x + threadIdx.x;
    if (i < E) atomicAdd(&deg[dst[i]], 1);
}

__global__ void __launch_bounds__(1024) scan_kernel(const int* __restrict__ deg,
                                                    int* __restrict__ rowptr,
                                                    int* __restrict__ cursor, int N)
{
    __shared__ int sums[32];
    __shared__ int carry;
    int tid = threadIdx.x;
    if (tid == 0) carry = 0;
    __syncthreads();
    for (int base = 0; base < N; base += 1024) {
        int i = base + tid;
        int v = (i < N) ? deg[i] : 0;
        int x = v;
        #pragma unroll
        for (int o = 1; o < 32; o <<= 1) {
            int y = __shfl_up_sync(~0u, x, o);
            if ((tid & 31) >= o) x += y;
        }
        if ((tid & 31) == 31) sums[tid >> 5] = x;
        __syncthreads();
        if (tid < 32) {
            int s = sums[tid];
            #pragma unroll
            for (int o = 1; o < 32; o <<= 1) {
                int y = __shfl_up_sync(~0u, s, o);
                if (tid >= o) s += y;
            }
            sums[tid] = s;
        }
        __syncthreads();
        int incl = x + ((tid >= 32) ? sums[(tid >> 5) - 1] : 0) + carry;
        if (i < N) {
            rowptr[i + 1] = incl;
            cursor[i] = incl - v;
        }
        __syncthreads();
        if (tid == 1023) carry = incl;
        __syncthreads();
    }
    if (tid == 0) rowptr[0] = 0;
}

__global__ void scatter_kernel(const int* __restrict__ src, const int* __restrict__ dst,
                               int* __restrict__ cursor, int* __restrict__ col, int E)
{
    int i = blockIdx.x * blockDim.x + threadIdx.x;
    if (i >= E) return;
    int slot = atomicAdd(&cursor[dst[i]], 1);
    col[slot] = src[i];
}

// ---------------- GAT aggregate (fp16 h, templated output type) ----------
template<int H, int CPL, typename OutT>
__global__ void gat_aggregate(const int* __restrict__ rowptr, const int* __restrict__ col,
                              const float* __restrict__ asrc, const float* __restrict__ adst,
                              const __half* __restrict__ h, const float* __restrict__ bias,
                              OutT* __restrict__ out, int N)
{
    const int C = 32 * CPL;
    int warp = (blockIdx.x * blockDim.x + threadIdx.x) >> 5;
    int lane = threadIdx.x & 31;
    if (warp >= N * H) return;
    int d = warp / H, hh = warp % H;
    int beg = rowptr[d], end = rowptr[d + 1];
    float ad = adst[d * H + hh];

    float m = -INFINITY, den = 0.f;
    for (int i = beg + lane; i < end; i += 32) {
        float v = asrc[col[i] * H + hh] + ad;
        v = (v >= 0.f) ? v : 0.2f * v;
        if (v > m) { den = den * __expf(m - v) + 1.f; m = v; }
        else den += __expf(v - m);
    }
    #pragma unroll
    for (int o = 16; o; o >>= 1) {
        float m2 = __shfl_xor_sync(~0u, m, o);
        float d2 = __shfl_xor_sync(~0u, den, o);
        float nm = fmaxf(m, m2);
        float f1 = (m == nm) ? 1.f : __expf(m - nm);
        float f2 = (m2 == nm) ? 1.f : __expf(m2 - nm);
        den = den * f1 + d2 * f2;
        m = nm;
    }
    float inv = 1.f / (den + 1e-16f);

    float acc[CPL];
    #pragma unroll
    for (int q = 0; q < CPL; q++) acc[q] = 0.f;

    for (int base = beg; base < end; base += 32) {
        int i = base + lane;
        int s = 0; float coef = 0.f;
        if (i < end) {
            s = col[i];
            float v = asrc[s * H + hh] + ad;
            v = (v >= 0.f) ? v : 0.2f * v;
            coef = __expf(v - m) * inv;
        }
        int cnt = min(32, end - base);
        for (int j = 0; j < cnt; j++) {
            int sj = __shfl_sync(~0u, s, j);
            float cj = __shfl_sync(~0u, coef, j);
            const __half* hp = h + ((size_t)sj * H + hh) * C + lane * CPL;
            if (CPL == 4) {
                uint2 raw = *(const uint2*)hp;
                float2 p0 = __half22float2(*(const __half2*)&raw.x);
                float2 p1 = __half22float2(*(const __half2*)&raw.y);
                acc[0] += cj * p0.x; acc[1] += cj * p0.y;
                acc[2] += cj * p1.x; acc[3] += cj * p1.y;
            } else {
                uint32_t raw = *(const uint32_t*)hp;
                float2 p0 = __half22float2(*(const __half2*)&raw);
                acc[0] += cj * p0.x; acc[1] += cj * p0.y;
            }
        }
    }

    OutT* op = out + ((size_t)d * H + hh) * C + lane * CPL;
    const float* bp = bias + hh * C + lane * CPL;
    #pragma unroll
    for (int q = 0; q < CPL; q++) {
        float v = fmaxf(acc[q] + bp[q], 0.f);
        op[q] = (OutT)v;
    }
}

// ================= final GEMM: out = xf @ yf^T (fp16 m16n8k16) =============
#define BSTR 72
__global__ void __launch_bounds__(256) final_mma_kernel(
    const __half* __restrict__ A, const __half* __restrict__ B, float* __restrict__ C)
{
    __shared__ __half As[128 * BSTR];
    __shared__ __half Bs[128 * BSTR];

    const int tid = threadIdx.x, wid = tid >> 5, lane = tid & 31;
    const int g = lane >> 2, t = lane & 3;
    const int wm = wid & 3, wn = wid >> 2;
    const int m0 = blockIdx.y * 128, n0 = blockIdx.x * 128;

    {
        const __half* Ag = A + (size_t)m0 * 64;
        const __half* Bg = B + (size_t)n0 * 64;
        #pragma unroll
        for (int i = tid; i < 1024; i += 256) {
            int row = i >> 3, c8 = (i & 7) << 3;
            uint4 v = *(const uint4*)(Ag + (size_t)row * 64 + c8);
            *(uint4*)&As[row * BSTR + c8] = v;
        }
        #pragma unroll
        for (int i = tid; i < 1024; i += 256) {
            int row = i >> 3, c8 = (i & 7) << 3;
            uint4 v = *(const uint4*)(Bg + (size_t)row * 64 + c8);
            *(uint4*)&Bs[row * BSTR + c8] = v;
        }
    }
    __syncthreads();

    float acc[2][8][4];
    #pragma unroll
    for (int i = 0; i < 2; i++)
        #pragma unroll
        for (int j = 0; j < 8; j++)
            #pragma unroll
            for (int q = 0; q < 4; q++) acc[i][j][q] = 0.f;

    #pragma unroll
    for (int ks = 0; ks < 4; ks++) {
        const int kb = ks * 16;
        uint32_t a[2][4];
        #pragma unroll
        for (int mf = 0; mf < 2; mf++) {
            int r = wm * 32 + mf * 16;
            a[mf][0] = *(const uint32_t*)&As[(r + g)     * BSTR + kb + 2 * t];
            a[mf][1] = *(const uint32_t*)&As[(r + g + 8) * BSTR + kb + 2 * t];
            a[mf][2] = *(const uint32_t*)&As[(r + g)     * BSTR + kb + 2 * t + 8];
            a[mf][3] = *(const uint32_t*)&As[(r + g + 8) * BSTR + kb + 2 * t + 8];
        }
        #pragma unroll
        for (int nf = 0; nf < 8; nf++) {
            int n = wn * 64 + nf * 8 + g;
            uint32_t b[2];
            b[0] = *(const uint32_t*)&Bs[n * BSTR + kb + 2 * t];
            b[1] = *(const uint32_t*)&Bs[n * BSTR + kb + 2 * t + 8];
            mma_f16(acc[0][nf], a[0], b);
            mma_f16(acc[1][nf], a[1], b);
        }
    }

    #pragma unroll
    for (int mf = 0; mf < 2; mf++) {
        #pragma unroll
        for (int rr = 0; rr < 2; rr++) {
            int row = m0 + wm * 32 + mf * 16 + rr * 8 + g;
            if (row >= M_NODES) continue;
            float* cp = C + (size_t)row * D_NODES;
            #pragma unroll
            for (int nf = 0; nf < 8; nf++) {
                int col = n0 + wn * 64 + nf * 8 + 2 * t;
                if (col < D_NODES) {
                    float2 v;
                    v.x = acc[mf][nf][rr * 2 + 0];
                    v.y = acc[mf][nf][rr * 2 + 1];
                    *(float2*)(cp + col) = v;
                }
            }
        }
    }
}

// ---------------- host orchestration ----------------
static void run_gemm(const float* A, const float* B, const float* bias, float* C,
                     int N, int K, int Cn, int act, cudaStream_t st, int out_half = 0,
                     const float* a_s = nullptr, const float* a_d = nullptr,
                     float* asrc = nullptr, float* adst = nullptr,
                     int H = 1, int Chead = 64)
{
    dim3 g(Cn / 64, (N + 127) / 128);
    mma_gemm_kernel<<<g, 256, 0, st>>>(A, B, bias, C, N, K, Cn, act, out_half,
                                       a_s, a_d, asrc, adst, H, Chead);
}

static void run_hgemm(const __half* A, const float* B, const float* bias, __half* C,
                      int N, int K, int Cn, cudaStream_t st)
{
    dim3 g(Cn / 64, (N + 127) / 128);
    hgemm_kernel<<<g, 256, 0, st>>>(A, B, bias, C, N, K, Cn, 1);
}

static void build_csr(const int* ei, int E, int N, int* rowptr, int* col,
                      int* cursor, int* deg, cudaStream_t st)
{
    const int* src = ei;
    const int* dst = ei + E;
    cudaMemsetAsync(deg, 0, N * sizeof(int), st);
    hist_kernel<<<(E + 255) / 256, 256, 0, st>>>(dst, deg, E);
    scan_kernel<<<1, 1024, 0, st>>>(deg, rowptr, cursor, N);
    scatter_kernel<<<(E + 255) / 256, 256, 0, st>>>(src, dst, cursor, col, E);
}

extern "C" void kernel_launch(void* const* d_in, const int* in_sizes, int n_in,
                              void* d_out, int out_size)
{
    const float* x_m  = (const float*)d_in[0];
    const float* x_d  = (const float*)d_in[1];
    const int*   mm   = (const int*)d_in[2];
    const int*   dd   = (const int*)d_in[3];
    const float* W_gx1 = (const float*)d_in[4];
    const float* as_gx1 = (const float*)d_in[5];
    const float* ad_gx1 = (const float*)d_in[6];
    const float* b_gx1  = (const float*)d_in[7];
    const float* W_gx2 = (const float*)d_in[8];
    const float* as_gx2 = (const float*)d_in[9];
    const float* ad_gx2 = (const float*)d_in[10];
    const float* b_gx2  = (const float*)d_in[11];
    const float* W_gy1 = (const float*)d_in[12];
    const float* as_gy1 = (const float*)d_in[13];
    const float* ad_gy1 = (const float*)d_in[14];
    const float* b_gy1  = (const float*)d_in[15];
    const float* W_gy2 = (const float*)d_in[16];
    const float* as_gy2 = (const float*)d_in[17];
    const float* ad_gy2 = (const float*)d_in[18];
    const float* b_gy2  = (const float*)d_in[19];
    const float* lx1_W = (const float*)d_in[20];
    const float* lx1_b = (const float*)d_in[21];
    const float* lx2_W = (const float*)d_in[22];
    const float* lx2_b = (const float*)d_in[23];
    const float* lx3_W = (const float*)d_in[24];
    const float* lx3_b = (const float*)d_in[25];
    const float* ly1_W = (const float*)d_in[26];
    const float* ly1_b = (const float*)d_in[27];
    const float* ly2_W = (const float*)d_in[28];
    const float* ly2_b = (const float*)d_in[29];
    const float* ly3_W = (const float*)d_in[30];
    const float* ly3_b = (const float*)d_in[31];

    float *feat, *asrc, *adst;
    float *featY, *asrcY, *adstY;
    __half *h, *hY, *X, *t1, *t2, *xfh, *XY, *t1Y, *t2Y, *yfh;
    int *rpA, *colA, *curA, *degA, *rpB, *colB, *curB, *degB;
    cudaGetSymbolAddress((void**)&h,    g_h);
    cudaGetSymbolAddress((void**)&feat, g_feat);
    cudaGetSymbolAddress((void**)&asrc, g_asrc);
    cudaGetSymbolAddress((void**)&adst, g_adst);
    cudaGetSymbolAddress((void**)&X,    g_X);
    cudaGetSymbolAddress((void**)&t1,   g_t1);
    cudaGetSymbolAddress((void**)&t2,   g_t2);
    cudaGetSymbolAddress((void**)&xfh,  g_xfh);
    cudaGetSymbolAddress((void**)&rpA,  g_rpA);
    cudaGetSymbolAddress((void**)&colA, g_colA);
    cudaGetSymbolAddress((void**)&curA, g_curA);
    cudaGetSymbolAddress((void**)&degA, g_degA);
    cudaGetSymbolAddress((void**)&hY,    g_hY);
    cudaGetSymbolAddress((void**)&featY, g_featY);
    cudaGetSymbolAddress((void**)&asrcY, g_asrcY);
    cudaGetSymbolAddress((void**)&adstY, g_adstY);
    cudaGetSymbolAddress((void**)&XY,    g_XY);
    cudaGetSymbolAddress((void**)&t1Y,   g_t1Y);
    cudaGetSymbolAddress((void**)&t2Y,   g_t2Y);
    cudaGetSymbolAddress((void**)&yfh,   g_yfh);
    cudaGetSymbolAddress((void**)&rpB,  g_rpB);
    cudaGetSymbolAddress((void**)&colB, g_colB);
    cudaGetSymbolAddress((void**)&curB, g_curB);
    cudaGetSymbolAddress((void**)&degB, g_degB);

    static cudaStream_t sY = 0, sC = 0;
    static cudaEvent_t eFork = 0, eJoin = 0, eCsr = 0;
    static bool inited = false, forked = false;
    if (!inited) {
        inited = true;
        forked = (cudaStreamCreateWithFlags(&sY, cudaStreamNonBlocking) == cudaSuccess)
              && (cudaStreamCreateWithFlags(&sC, cudaStreamNonBlocking) == cudaSuccess)
              && (cudaEventCreateWithFlags(&eFork, cudaEventDisableTiming) == cudaSuccess)
              && (cudaEventCreateWithFlags(&eJoin, cudaEventDisableTiming) == cudaSuccess)
              && (cudaEventCreateWithFlags(&eCsr,  cudaEventDisableTiming) == cudaSuccess);
    }
    cudaStream_t sy = forked ? sY : 0;
    cudaStream_t sc = forked ? sC : 0;
    if (forked) {
        cudaEventRecord(eFork, 0);
        cudaStreamWaitEvent(sY, eFork, 0);
        cudaStreamWaitEvent(sC, eFork, 0);
    }

    // ----- X CSR build (side stream sc) -----
    build_csr(mm, E_MM, M_NODES, rpA, colA, curA, degA, sc);
    if (forked) cudaEventRecord(eCsr, sC);

    // ----- X branch (stream 0) -----
    cudaMemsetAsync(xfh + (size_t)M_NODES * 64, 0,
                    (size_t)(MPAD - M_NODES) * 64 * sizeof(__half), 0);
    cudaMemsetAsync(asrc, 0, M_NODES * 2 * sizeof(float), 0);
    cudaMemsetAsync(adst, 0, M_NODES * 2 * sizeof(float), 0);
    run_gemm(x_m, W_gx1, nullptr, (float*)h, M_NODES, 64, 256, 0, 0, 1,
             as_gx1, ad_gx1, asrc, adst, 2, 128);
    if (forked) cudaStreamWaitEvent(0, eCsr, 0);
    gat_aggregate<2, 4, float><<<(M_NODES * 2 + 7) / 8, 256, 0, 0>>>(rpA, colA, asrc, adst, h, b_gx1, feat, M_NODES);
    cudaMemsetAsync(asrc, 0, M_NODES * sizeof(float), 0);
    cudaMemsetAsync(adst, 0, M_NODES * sizeof(float), 0);
    run_gemm(feat, W_gx2, nullptr, (float*)h, M_NODES, 256, 64, 0, 0, 1,
             as_gx2, ad_gx2, asrc, adst, 1, 64);
    gat_aggregate<1, 2, __half><<<(M_NODES + 7) / 8, 256, 0, 0>>>(rpA, colA, asrc, adst, h, b_gx2, X, M_NODES);
    run_hgemm(X,  lx1_W, lx1_b, t1, M_NODES, 64,  256, 0);
    run_hgemm(t1, lx2_W, lx2_b, t2, M_NODES, 256, 128, 0);
    run_hgemm(t2, lx3_W, lx3_b, xfh, M_NODES, 128, 64, 0);

    // ----- Y branch (side stream sy) -----
    cudaMemsetAsync(yfh + (size_t)D_NODES * 64, 0,
                    (size_t)(DPAD - D_NODES) * 64 * sizeof(__half), sy);
    build_csr(dd, E_DD, D_NODES, rpB, colB, curB, degB, sy);
    cudaMemsetAsync(asrcY, 0, D_NODES * 2 * sizeof(float), sy);
    cudaMemsetAsync(adstY, 0, D_NODES * 2 * sizeof(float), sy);
    run_gemm(x_d, W_gy1, nullptr, (float*)hY, D_NODES, 64, 256, 0, sy, 1,
             as_gy1, ad_gy1, asrcY, adstY, 2, 128);
    gat_aggregate<2, 4, float><<<(D_NODES * 2 + 7) / 8, 256, 0, sy>>>(rpB, colB, asrcY, adstY, hY, b_gy1, featY, D_NODES);
    cudaMemsetAsync(asrcY, 0, D_NODES * sizeof(float), sy);
    cudaMemsetAsync(adstY, 0, D_NODES * sizeof(float), sy);
    run_gemm(featY, W_gy2, nullptr, (float*)hY, D_NODES, 256, 64, 0, sy, 1,
             as_gy2, ad_gy2, asrcY, adstY, 1, 64);
    gat_aggregate<1, 2, __half><<<(D_NODES + 7) / 8, 256, 0, sy>>>(rpB, colB, asrcY, adstY, hY, b_gy2, XY, D_NODES);
    run_hgemm(XY,  ly1_W, ly1_b, t1Y, D_NODES, 64,  256, sy);
    run_hgemm(t1Y, ly2_W, ly2_b, t2Y, D_NODES, 256, 128, sy);
    run_hgemm(t2Y, ly3_W, ly3_b, yfh, D_NODES, 128, 64, sy);

    if (forked) {
        cudaEventRecord(eJoin, sY);
        cudaStreamWaitEvent(0, eJoin, 0);
    }

    // ----- final: out = xf @ yf^T (fp16 operands, f32 accum/output) -----
    dim3 grid(DPAD / 128, MPAD / 128);   // 63 x 157
    final_mma_kernel<<<grid, 256, 0, 0>>>(xfh, yfh, (float*)d_out);
}